// round 7
// baseline (speedup 1.0000x reference)
#include <cuda_runtime.h>
#include <cuda_fp16.h>
#include <cstdint>

#define B_   16
#define T_   1024
#define E_   256
#define NB_  1025
#define BT_  16384
#define NE_  1024

#define ZQ_SIZE  (BT_ * E_)
#define LOSS_OFF ZQ_SIZE
#define IND_OFF  (ZQ_SIZE + 1)
#define V_OFF    (IND_OFF + BT_)

#define DSTRIDE  1152
#define NTILES_N 9               // 9 * 128 = 1152 cols
#define NTILES_R 128             // 128 * 128 = 16384 rows
#define NGEMM    (NTILES_N * NTILES_R)
#define NPOST    2048

#define K_EXT    768             // 3 products x K=256 (fp16 split)
#define KCH      32
#define NCH      (K_EXT / KCH)   // 24
#define ASTRIDE  40              // half elements per smem row (80 B)

#define SD 10
#define SW 16

typedef unsigned long long ull;

__device__ int    g_ind[BT_];
__device__ float  g_zsq[BT_];
__device__ float  g_bsq[DSTRIDE];
__device__ float  g_d[BT_ * DSTRIDE];
__device__ double g_part[NPOST];
__device__ int    g_rowflag[NTILES_R];          // rb = tc*16 + b ; 9 tiles each
__device__ __half a_ext[(size_t)BT_ * K_EXT];   // 24 MB
__device__ __half b_ext[(size_t)NB_ * K_EXT];   // 1.5 MB

static __device__ __forceinline__ float warp_sum(float v) {
#pragma unroll
    for (int o = 16; o > 0; o >>= 1) v += __shfl_xor_sync(0xffffffffu, v, o);
    return v;
}

static __device__ __forceinline__ uint32_t smem_u32(const void* p) {
    uint32_t a;
    asm("{ .reg .u64 t; cvta.to.shared.u64 t, %1; cvt.u32.u64 %0, t; }"
        : "=r"(a) : "l"(p));
    return a;
}

static __device__ __forceinline__ int ld_acq(const int* p) {
    int v;
    asm volatile("ld.acquire.gpu.global.s32 %0, [%1];" : "=r"(v) : "l"(p));
    return v;
}

#define CP16(dst, src) \
    asm volatile("cp.async.cg.shared.global [%0], [%1], 16;" :: "r"(dst), "l"(src))
#define CP16S(dst, src, sz) \
    asm volatile("cp.async.cg.shared.global [%0], [%1], 16, %2;" :: "r"(dst), "l"(src), "r"(sz))
#define CPCOMMIT() asm volatile("cp.async.commit_group;" ::: "memory")
#define CPWAIT(N)  asm volatile("cp.async.wait_group %0;" :: "n"(N) : "memory")

#define LDSM4(r0, r1, r2, r3, addr) \
    asm volatile("ldmatrix.sync.aligned.m8n8.x4.shared.b16 {%0,%1,%2,%3}, [%4];" \
                 : "=r"(r0), "=r"(r1), "=r"(r2), "=r"(r3) : "r"(addr))

static __device__ __forceinline__ void mma16816(float* c, const unsigned* a,
                                                unsigned b0, unsigned b1) {
    asm volatile(
        "mma.sync.aligned.m16n8k16.row.col.f32.f16.f16.f32 "
        "{%0,%1,%2,%3}, {%4,%5,%6,%7}, {%8,%9}, {%0,%1,%2,%3};"
        : "+f"(c[0]), "+f"(c[1]), "+f"(c[2]), "+f"(c[3])
        : "r"(a[0]), "r"(a[1]), "r"(a[2]), "r"(a[3]), "r"(b0), "r"(b1));
}

// ---------------------------------------------------------------------------
// k_prep: fused row norms + fp16 2-way split + flag reset.
// A_ext segs: [z0, z0, z1]; B_ext segs: [w0, w1, w0]
// ---------------------------------------------------------------------------
__global__ void k_prep(const float* __restrict__ z, const float* __restrict__ w) {
    if (blockIdx.x == 0 && threadIdx.x < NTILES_R) g_rowflag[threadIdx.x] = 0;
    int gw = (blockIdx.x * blockDim.x + threadIdx.x) >> 5;
    int lane = threadIdx.x & 31;
    if (gw >= BT_ + NB_) return;

    const float* src = (gw < BT_) ? (z + (size_t)gw * E_ + lane * 8)
                                  : (w + (size_t)(gw - BT_) * E_ + lane * 8);
    float4 a = *(const float4*)src;
    float4 b = *(const float4*)(src + 4);
    float f[8] = {a.x, a.y, a.z, a.w, b.x, b.y, b.z, b.w};

    float s = 0.0f;
    union { __half h[8]; uint4 v; } hi, lo;
#pragma unroll
    for (int j = 0; j < 8; j++) {
        s += f[j] * f[j];
        __half h = __float2half_rn(f[j]);
        hi.h[j] = h;
        lo.h[j] = __float2half_rn(f[j] - __half2float(h));
    }
    s = warp_sum(s);

    if (gw < BT_) {
        __half* base = a_ext + (size_t)gw * K_EXT + lane * 8;
        *(uint4*)(base)       = hi.v;
        *(uint4*)(base + 256) = hi.v;
        *(uint4*)(base + 512) = lo.v;
        if (lane == 0) g_zsq[gw] = s;
    } else {
        __half* base = b_ext + (size_t)(gw - BT_) * K_EXT + lane * 8;
        *(uint4*)(base)       = hi.v;
        *(uint4*)(base + 256) = lo.v;
        *(uint4*)(base + 512) = hi.v;
        if (lane == 0) g_bsq[gw - BT_] = s;
    }
}

// ---------------------------------------------------------------------------
// argmin over d[b,0,:]
// ---------------------------------------------------------------------------
__global__ void k_first(const float* __restrict__ z, const float* __restrict__ w) {
    int b = blockIdx.x;
    __shared__ __align__(16) float zs[E_];
    __shared__ float sd[8];
    __shared__ int   sn[8];
    int tid = threadIdx.x;
    zs[tid] = z[(size_t)b * T_ * E_ + tid];
    __syncthreads();

    float zsq0 = g_zsq[b * T_];
    int warp = tid >> 5, lane = tid & 31;
    float4 za = *(const float4*)(zs + 4 * lane);
    float4 zb = *(const float4*)(zs + 128 + 4 * lane);

    float best = 3.4e38f;
    int bestn = 0x7fffffff;
    for (int n = warp; n < NB_; n += 8) {
        const float* wr = w + (size_t)n * E_;
        float4 wa = *(const float4*)(wr + 4 * lane);
        float4 wb = *(const float4*)(wr + 128 + 4 * lane);
        float p = za.x * wa.x + za.y * wa.y + za.z * wa.z + za.w * wa.w
                + zb.x * wb.x + zb.y * wb.y + zb.z * wb.z + zb.w * wb.w;
        p = warp_sum(p);
        float d = (zsq0 + g_bsq[n]) - 2.0f * p;
        if (d < best || (d == best && n < bestn)) { best = d; bestn = n; }
    }
    if (lane == 0) { sd[warp] = best; sn[warp] = bestn; }
    __syncthreads();
    if (tid == 0) {
        float bd = sd[0]; int bn = sn[0];
        for (int j = 1; j < 8; j++)
            if (sd[j] < bd || (sd[j] == bd && sn[j] < bn)) { bd = sd[j]; bn = sn[j]; }
        g_ind[b * T_] = min(bn, NE_ - 1);
    }
}

// ---------------------------------------------------------------------------
// Mega kernel. Block 0: cp.async scan trailing the GEMM via row flags.
// Blocks [1, 1+1152): R6 HMMA split-GEMM, t-chunk-round-robin tile order,
// releasing g_rowflag[rb] per tile.
// ---------------------------------------------------------------------------
union MegaSmem {
    struct { __half As[2][128][ASTRIDE]; __half Bs[2][128][ASTRIDE]; } g; // 40960 B
    struct { float buf[16][SD * SW + 4]; int bb[16][SD]; } s;             // 11136 B
};

__global__ void __launch_bounds__(256) k_mega() {
    __shared__ __align__(16) MegaSmem sm;
    int tid = threadIdx.x;

    if (blockIdx.x == 0) {
        // ---------------- scan path ----------------
        int b = tid;
        if (b >= 16) return;

        int ia = g_ind[b * T_];
        float coe = 0.0f;
        const float PC = 0.1f / 1024.0f;
        int ready_hi = 0;   // rows [0, ready_hi) of batch b are ready

#define WAITROW(tt)                                                        \
        while ((tt) >= ready_hi) {                                         \
            int fidx = ((ready_hi >> 7) << 4) + b;                         \
            while (ld_acq(&g_rowflag[fidx]) < NTILES_N) __nanosleep(64);   \
            ready_hi += 128;                                               \
        }

        WAITROW(SD);
        int ab0 = ia & ~3;
#pragma unroll
        for (int p = 1; p <= SD; ++p) {
            int slot = p % SD;
            const char* src = (const char*)(g_d + (size_t)(b * T_ + p) * DSTRIDE + ab0);
            uint32_t dst = smem_u32(&sm.s.buf[b][slot * SW]);
            CP16(dst, src);
            CP16(dst + 16, src + 16);
            CP16(dst + 32, src + 32);
            CP16(dst + 48, src + 48);
            sm.s.bb[b][slot] = ab0;
            CPCOMMIT();
        }

        int slot = 1 % SD;
        int bas = ab0;
        for (int t = 1; t < T_; ++t) {
            CPWAIT(SD - 1);
            int off = ia - bas;
            int ib = min(ia + 1, NE_ - 1);
            float d_here = sm.s.buf[b][slot * SW + off];
            float d_next = sm.s.buf[b][slot * SW + (ib - bas)];
            bool stay = (d_here <= d_next - coe);
            ia  = stay ? ia : ib;
            coe = stay ? coe + PC : 0.0f;
            g_ind[b * T_ + t] = ia;

            int nslot = (slot + 1 == SD) ? 0 : slot + 1;
            bas = sm.s.bb[b][nslot];

            int ts = t + SD;
            if (ts < T_) {
                WAITROW(ts);
                int ab = ia & ~3;
                const char* src = (const char*)(g_d + (size_t)(b * T_ + ts) * DSTRIDE + ab);
                uint32_t dst = smem_u32(&sm.s.buf[b][slot * SW]);
                CP16(dst, src);
                CP16(dst + 16, src + 16);
                CP16(dst + 32, src + 32);
                CP16(dst + 48, src + 48);
                sm.s.bb[b][slot] = ab;
            }
            CPCOMMIT();
            slot = nslot;
        }
#undef WAITROW
        return;
    }

    // ---------------- GEMM path (R6 kernel, remapped tiles) ----------------
    int wid = tid >> 5;
    int lane = tid & 31;
    int warp_m = wid & 3;
    int warp_n = wid >> 2;

    int gi = blockIdx.x - 1;
    int nt0 = gi % NTILES_N;
    int rb  = gi / NTILES_N;            // rb = tc*16 + b
    int row0 = (rb & 15) * T_ + (rb >> 4) * 128;
    int n0   = nt0 * 128;

    float acc[2][8][4];
#pragma unroll
    for (int i = 0; i < 2; i++)
#pragma unroll
        for (int j = 0; j < 8; j++)
#pragma unroll
            for (int k = 0; k < 4; k++) acc[i][j][k] = 0.0f;

    uint32_t a_base = smem_u32(&sm.g.As[0][0][0]);
    uint32_t b_base = smem_u32(&sm.g.Bs[0][0][0]);
    const uint32_t STAGE_BYTES = 128 * ASTRIDE * 2;

    int ch0 = tid * 2, ch1 = tid * 2 + 1;
    int ar0 = ch0 >> 2, as0 = ch0 & 3;
    int ar1 = ch1 >> 2, as1 = ch1 & 3;
    int bn0_ = n0 + ar0, bn1_ = n0 + ar1;
    const __half* apz  = a_ext + (size_t)(row0 + ar0) * K_EXT + as0 * 8;
    const __half* apz1 = a_ext + (size_t)(row0 + ar1) * K_EXT + as1 * 8;
    const __half* bpz  = b_ext + (size_t)(bn0_ < NB_ ? bn0_ : NB_ - 1) * K_EXT + as0 * 8;
    const __half* bpz1 = b_ext + (size_t)(bn1_ < NB_ ? bn1_ : NB_ - 1) * K_EXT + as1 * 8;
    uint32_t adst0 = a_base + ar0 * (ASTRIDE * 2) + as0 * 16;
    uint32_t adst1 = a_base + ar1 * (ASTRIDE * 2) + as1 * 16;
    uint32_t bdst0 = b_base + ar0 * (ASTRIDE * 2) + as0 * 16;
    uint32_t bdst1 = b_base + ar1 * (ASTRIDE * 2) + as1 * 16;
    uint32_t bsz0 = bn0_ < NB_ ? 16u : 0u;
    uint32_t bsz1 = bn1_ < NB_ ? 16u : 0u;

#define LOADCH(c, buf)                                                       \
    {                                                                        \
        uint32_t so = (buf) * STAGE_BYTES;                                   \
        int ko = (c) * KCH;                                                  \
        CP16(adst0 + so, (const char*)(apz + ko));                           \
        CP16(adst1 + so, (const char*)(apz1 + ko));                          \
        CP16S(bdst0 + so, (const char*)(bpz + ko), bsz0);                    \
        CP16S(bdst1 + so, (const char*)(bpz1 + ko), bsz1);                   \
        CPCOMMIT();                                                          \
    }

    LOADCH(0, 0);

    int lrow = lane & 15;
    int lcol8 = (lane >> 4) * 8;
    uint32_t a_lm = a_base + (warp_m * 32 + lrow) * (ASTRIDE * 2) + lcol8 * 2;
    uint32_t b_lm = b_base + (warp_n * 64 + lrow) * (ASTRIDE * 2) + lcol8 * 2;

#pragma unroll 1
    for (int c = 0; c < NCH; ++c) {
        int p = c & 1;
        if (c + 1 < NCH) {
            LOADCH(c + 1, 1 - p);
            CPWAIT(1);
        } else {
            CPWAIT(0);
        }
        __syncthreads();
        uint32_t so = p * STAGE_BYTES;
#pragma unroll
        for (int ks = 0; ks < 2; ks++) {
            unsigned af[2][4];
#pragma unroll
            for (int mt = 0; mt < 2; mt++)
                LDSM4(af[mt][0], af[mt][1], af[mt][2], af[mt][3],
                      a_lm + so + mt * 16 * (ASTRIDE * 2) + ks * 32);
            unsigned bf[4][4];
#pragma unroll
            for (int np = 0; np < 4; np++)
                LDSM4(bf[np][0], bf[np][1], bf[np][2], bf[np][3],
                      b_lm + so + np * 16 * (ASTRIDE * 2) + ks * 32);
#pragma unroll
            for (int mt = 0; mt < 2; mt++)
#pragma unroll
                for (int ntile = 0; ntile < 8; ntile++)
                    mma16816(acc[mt][ntile], af[mt],
                             bf[ntile >> 1][ntile & 1],
                             bf[ntile >> 1][(ntile & 1) + 2]);
        }
        __syncthreads();
    }

    // epilogue: d = zsq + bsq - 2*cross
    int rbase = row0 + warp_m * 32;
    int cbase = n0 + warp_n * 64;
    int rlo = rbase + (lane >> 2);
    int csub = (lane & 3) * 2;
#pragma unroll
    for (int mt = 0; mt < 2; mt++) {
        int r0 = rlo + mt * 16;
        int r1 = r0 + 8;
        float zs0 = g_zsq[r0], zs1 = g_zsq[r1];
        float* dp0 = g_d + (size_t)r0 * DSTRIDE;
        float* dp1 = g_d + (size_t)r1 * DSTRIDE;
#pragma unroll
        for (int ntile = 0; ntile < 8; ntile++) {
            int col = cbase + ntile * 8 + csub;
            float b0 = g_bsq[col], b1 = g_bsq[col + 1];
            float2 v0, v1;
            v0.x = (zs0 + b0) - 2.0f * acc[mt][ntile][0];
            v0.y = (zs0 + b1) - 2.0f * acc[mt][ntile][1];
            v1.x = (zs1 + b0) - 2.0f * acc[mt][ntile][2];
            v1.y = (zs1 + b1) - 2.0f * acc[mt][ntile][3];
            *(float2*)(dp0 + col) = v0;
            *(float2*)(dp1 + col) = v1;
        }
    }

    // release this tile for the scan
    __threadfence();
    __syncthreads();
    if (tid == 0) atomicAdd(&g_rowflag[rb], 1);
#undef LOADCH
}

// ---------------------------------------------------------------------------
// k_post: gather z_q + indices + li, relu-sum loss over d rows
// ---------------------------------------------------------------------------
__global__ void __launch_bounds__(256) k_post(const float* __restrict__ z,
                                              const float* __restrict__ w,
                                              float* __restrict__ out,
                                              long long out_size) {
    __shared__ double wpart[8];
    int warp = threadIdx.x >> 5;
    int lane = threadIdx.x & 31;
    int row = blockIdx.x * 8 + warp;

    int idx = g_ind[row];
    const float* br = w + (size_t)idx * E_;
    const float* zrow = z + (size_t)row * E_;
    bool wz = (out_size >= (long long)ZQ_SIZE);

    float li = 0.0f;
#pragma unroll
    for (int h = 0; h < 2; h++) {
        int off = h * 128 + 4 * lane;
        float4 q  = *(const float4*)(br + off);
        float4 zv = *(const float4*)(zrow + off);
        float4 o;
        o.x = zv.x + (q.x - zv.x);
        o.y = zv.y + (q.y - zv.y);
        o.z = zv.z + (q.z - zv.z);
        o.w = zv.w + (q.w - zv.w);
        float dx = zv.x - q.x; li += dx * dx;
        dx = zv.y - q.y; li += dx * dx;
        dx = zv.z - q.z; li += dx * dx;
        dx = zv.w - q.w; li += dx * dx;
        if (wz) *(float4*)(out + (size_t)row * E_ + off) = o;
    }
    li = warp_sum(li);
    li = __shfl_sync(0xffffffffu, li, 0);
    if (lane == 0 && out_size >= (long long)(IND_OFF + BT_))
        out[IND_OFF + row] = (float)idx;

    const float EPS_ = 1e-6f / 1024.0f;
    const float* drow = g_d + (size_t)row * DSTRIDE;
    float s = 0.0f;
#pragma unroll
    for (int m = 0; m < 8; m++) {
        float4 dv = *(const float4*)(drow + m * 128 + 4 * lane);
        s += fmaxf((li - dv.x) + EPS_, 0.0f);
        s += fmaxf((li - dv.y) + EPS_, 0.0f);
        s += fmaxf((li - dv.z) + EPS_, 0.0f);
        s += fmaxf((li - dv.w) + EPS_, 0.0f);
    }
    if (lane == 0) s += fmaxf((li - drow[1024]) + EPS_, 0.0f);
    s = warp_sum(s);
    if (lane == 0) wpart[warp] = (double)s;
    __syncthreads();
    if (threadIdx.x == 0) {
        double t = 0.0;
        for (int j = 0; j < 8; j++) t += wpart[j];
        g_part[blockIdx.x] = t;
    }
}

// ---------------------------------------------------------------------------
__global__ void k_final(float* __restrict__ out, long long out_size) {
    __shared__ double sd[256];
    __shared__ int smn[256], smx[256];
    int tid = threadIdx.x;
    double s = 0.0;
    for (int i = tid; i < NPOST; i += 256) s += g_part[i];
    int mn = 0x7fffffff, mx = -0x7fffffff;
    for (int i = tid; i < BT_; i += 256) {
        int v = g_ind[i];
        mn = min(mn, v);
        mx = max(mx, v);
    }
    sd[tid] = s; smn[tid] = mn; smx[tid] = mx;
    __syncthreads();
    for (int st = 128; st > 0; st >>= 1) {
        if (tid < st) {
            sd[tid] += sd[tid + st];
            smn[tid] = min(smn[tid], smn[tid + st]);
            smx[tid] = max(smx[tid], smx[tid + st]);
        }
        __syncthreads();
    }
    if (tid == 0) {
        float m = (float)(sd[0] / ((double)BT_ * (double)NB_));
        float loss = 0.25f * m + m;
        if (out_size > (long long)LOSS_OFF) out[LOSS_OFF] = loss;
        if (out_size > (long long)V_OFF)    out[V_OFF] = (float)(smx[0] - smn[0]);
    }
}

// ---------------------------------------------------------------------------
extern "C" void kernel_launch(void* const* d_in, const int* in_sizes, int n_in,
                              void* d_out, int out_size) {
    const float* z = (const float*)d_in[0];
    const float* w = (const float*)d_in[1];
    if (n_in >= 2 && in_sizes[0] == NB_ * E_ && in_sizes[1] == BT_ * E_) {
        const float* tmp = z; z = w; w = tmp;
    }
    float* out = (float*)d_out;
    long long osz = (long long)out_size;

    k_prep<<<(BT_ + NB_ + 7) / 8, 256>>>(z, w);
    k_first<<<B_, 256>>>(z, w);
    k_mega<<<1 + NGEMM, 256>>>();
    k_post<<<NPOST, 256>>>(z, w, out, osz);
    k_final<<<1, 256>>>(out, osz);
}

// round 8
// speedup vs baseline: 1.2913x; 1.2913x over previous
#include <cuda_runtime.h>
#include <cuda_fp16.h>
#include <cstdint>

#define B_   16
#define T_   1024
#define E_   256
#define NB_  1025
#define BT_  16384
#define NE_  1024

#define ZQ_SIZE  (BT_ * E_)
#define LOSS_OFF ZQ_SIZE
#define IND_OFF  (ZQ_SIZE + 1)
#define V_OFF    (IND_OFF + BT_)

#define DSTRIDE  1024
#define NTILES_N 8               // 8 * 128 = 1024 cols (col 1024 handled in k_post)
#define NTILES_R 128             // 128 * 128 = 16384 rows
#define NGEMM    (NTILES_N * NTILES_R)
#define NPOST    2048

#define K_EXT    768             // 3 products x K=256 (fp16 split)
#define KCH      32
#define NCH      (K_EXT / KCH)   // 24
#define ASTRIDE  40              // half elements per smem row (80 B)

#define SD 6                     // scan pipeline depth
#define SW 12                    // floats per prefetch slot (48 B)

typedef unsigned long long ull;

__device__ int    g_ind[BT_];
__device__ float  g_zsq[BT_];
__device__ float  g_bsq[1152];
__device__ float  g_d[(size_t)BT_ * DSTRIDE];   // 64 MB
__device__ double g_part[NPOST];
__device__ __half a_ext[(size_t)BT_ * K_EXT];   // 24 MB
__device__ __half b_ext[(size_t)NB_ * K_EXT];   // 1.5 MB

static __device__ __forceinline__ float warp_sum(float v) {
#pragma unroll
    for (int o = 16; o > 0; o >>= 1) v += __shfl_xor_sync(0xffffffffu, v, o);
    return v;
}

static __device__ __forceinline__ uint32_t smem_u32(const void* p) {
    uint32_t a;
    asm("{ .reg .u64 t; cvta.to.shared.u64 t, %1; cvt.u32.u64 %0, t; }"
        : "=r"(a) : "l"(p));
    return a;
}

static __device__ __forceinline__ float lds_f(int addr) {
    float v;
    asm volatile("ld.shared.f32 %0, [%1];" : "=f"(v) : "r"(addr));
    return v;
}

static __device__ __forceinline__ int lds_i(int addr) {
    int v;
    asm volatile("ld.shared.s32 %0, [%1];" : "=r"(v) : "r"(addr));
    return v;
}

#define CP16(dst, src) \
    asm volatile("cp.async.cg.shared.global [%0], [%1], 16;" :: "r"(dst), "l"(src))
#define CPCOMMIT() asm volatile("cp.async.commit_group;" ::: "memory")
#define CPWAIT(N)  asm volatile("cp.async.wait_group %0;" :: "n"(N) : "memory")

#define LDSM4(r0, r1, r2, r3, addr) \
    asm volatile("ldmatrix.sync.aligned.m8n8.x4.shared.b16 {%0,%1,%2,%3}, [%4];" \
                 : "=r"(r0), "=r"(r1), "=r"(r2), "=r"(r3) : "r"(addr))

static __device__ __forceinline__ void mma16816(float* c, const unsigned* a,
                                                unsigned b0, unsigned b1) {
    asm volatile(
        "mma.sync.aligned.m16n8k16.row.col.f32.f16.f16.f32 "
        "{%0,%1,%2,%3}, {%4,%5,%6,%7}, {%8,%9}, {%0,%1,%2,%3};"
        : "+f"(c[0]), "+f"(c[1]), "+f"(c[2]), "+f"(c[3])
        : "r"(a[0]), "r"(a[1]), "r"(a[2]), "r"(a[3]), "r"(b0), "r"(b1));
}

// ---------------------------------------------------------------------------
// k_prep: fused row norms + fp16 2-way split.
// A_ext segs: [z0, z0, z1]; B_ext segs: [w0, w1, w0]
// ---------------------------------------------------------------------------
__global__ void k_prep(const float* __restrict__ z, const float* __restrict__ w) {
    int gw = (blockIdx.x * blockDim.x + threadIdx.x) >> 5;
    int lane = threadIdx.x & 31;
    if (gw >= BT_ + NB_) return;

    const float* src = (gw < BT_) ? (z + (size_t)gw * E_ + lane * 8)
                                  : (w + (size_t)(gw - BT_) * E_ + lane * 8);
    float4 a = *(const float4*)src;
    float4 b = *(const float4*)(src + 4);
    float f[8] = {a.x, a.y, a.z, a.w, b.x, b.y, b.z, b.w};

    float s = 0.0f;
    union { __half h[8]; uint4 v; } hi, lo;
#pragma unroll
    for (int j = 0; j < 8; j++) {
        s += f[j] * f[j];
        __half h = __float2half_rn(f[j]);
        hi.h[j] = h;
        lo.h[j] = __float2half_rn(f[j] - __half2float(h));
    }
    s = warp_sum(s);

    if (gw < BT_) {
        __half* base = a_ext + (size_t)gw * K_EXT + lane * 8;
        *(uint4*)(base)       = hi.v;
        *(uint4*)(base + 256) = hi.v;
        *(uint4*)(base + 512) = lo.v;
        if (lane == 0) g_zsq[gw] = s;
    } else {
        __half* base = b_ext + (size_t)(gw - BT_) * K_EXT + lane * 8;
        *(uint4*)(base)       = hi.v;
        *(uint4*)(base + 256) = lo.v;
        *(uint4*)(base + 512) = hi.v;
        if (lane == 0) g_bsq[gw - BT_] = s;
    }
}

// ---------------------------------------------------------------------------
// argmin over d[b,0,:]
// ---------------------------------------------------------------------------
__global__ void k_first(const float* __restrict__ z, const float* __restrict__ w) {
    int b = blockIdx.x;
    __shared__ __align__(16) float zs[E_];
    __shared__ float sd[8];
    __shared__ int   sn[8];
    int tid = threadIdx.x;
    zs[tid] = z[(size_t)b * T_ * E_ + tid];
    __syncthreads();

    float zsq0 = g_zsq[b * T_];
    int warp = tid >> 5, lane = tid & 31;
    float4 za = *(const float4*)(zs + 4 * lane);
    float4 zb = *(const float4*)(zs + 128 + 4 * lane);

    float best = 3.4e38f;
    int bestn = 0x7fffffff;
    for (int n = warp; n < NB_; n += 8) {
        const float* wr = w + (size_t)n * E_;
        float4 wa = *(const float4*)(wr + 4 * lane);
        float4 wb = *(const float4*)(wr + 128 + 4 * lane);
        float p = za.x * wa.x + za.y * wa.y + za.z * wa.z + za.w * wa.w
                + zb.x * wb.x + zb.y * wb.y + zb.z * wb.z + zb.w * wb.w;
        p = warp_sum(p);
        float d = (zsq0 + g_bsq[n]) - 2.0f * p;
        if (d < best || (d == best && n < bestn)) { best = d; bestn = n; }
    }
    if (lane == 0) { sd[warp] = best; sn[warp] = bestn; }
    __syncthreads();
    if (tid == 0) {
        float bd = sd[0]; int bn = sn[0];
        for (int j = 1; j < 8; j++)
            if (sd[j] < bd || (sd[j] == bd && sn[j] < bn)) { bd = sd[j]; bn = sn[j]; }
        g_ind[b * T_] = min(bn, NE_ - 1);
    }
}

// ---------------------------------------------------------------------------
// fp16 split-GEMM via mma.sync (m16n8k16). CTA 128x128, K_ext=768, kchunk 32,
// double-buffered cp.async. N = 1024 (col 1024 handled in k_post).
// ---------------------------------------------------------------------------
__global__ void __launch_bounds__(256) k_gemm() {
    __shared__ __align__(16) __half As[2][128][ASTRIDE];
    __shared__ __align__(16) __half Bs[2][128][ASTRIDE];

    int tid = threadIdx.x;
    int wid = tid >> 5;
    int lane = tid & 31;
    int warp_m = wid & 3;       // 0..3  -> 32-row slice
    int warp_n = wid >> 2;      // 0..1  -> 64-col slice

    int bid = blockIdx.x;
    int nt0 = bid % NTILES_N;
    int rt  = bid / NTILES_N;
    int row0 = rt * 128;
    int n0   = nt0 * 128;

    float acc[2][8][4];
#pragma unroll
    for (int i = 0; i < 2; i++)
#pragma unroll
        for (int j = 0; j < 8; j++)
#pragma unroll
            for (int k = 0; k < 4; k++) acc[i][j][k] = 0.0f;

    uint32_t a_base = smem_u32(&As[0][0][0]);
    uint32_t b_base = smem_u32(&Bs[0][0][0]);
    const uint32_t STAGE_BYTES = 128 * ASTRIDE * 2;

    int ch0 = tid * 2, ch1 = tid * 2 + 1;
    int ar0 = ch0 >> 2, as0 = ch0 & 3;
    int ar1 = ch1 >> 2, as1 = ch1 & 3;
    const __half* apz  = a_ext + (size_t)(row0 + ar0) * K_EXT + as0 * 8;
    const __half* apz1 = a_ext + (size_t)(row0 + ar1) * K_EXT + as1 * 8;
    const __half* bpz  = b_ext + (size_t)(n0 + ar0) * K_EXT + as0 * 8;
    const __half* bpz1 = b_ext + (size_t)(n0 + ar1) * K_EXT + as1 * 8;
    uint32_t adst0 = a_base + ar0 * (ASTRIDE * 2) + as0 * 16;
    uint32_t adst1 = a_base + ar1 * (ASTRIDE * 2) + as1 * 16;
    uint32_t bdst0 = b_base + ar0 * (ASTRIDE * 2) + as0 * 16;
    uint32_t bdst1 = b_base + ar1 * (ASTRIDE * 2) + as1 * 16;

#define LOADCH(c, buf)                                                       \
    {                                                                        \
        uint32_t so = (buf) * STAGE_BYTES;                                   \
        int ko = (c) * KCH;                                                  \
        CP16(adst0 + so, (const char*)(apz + ko));                           \
        CP16(adst1 + so, (const char*)(apz1 + ko));                          \
        CP16(bdst0 + so, (const char*)(bpz + ko));                           \
        CP16(bdst1 + so, (const char*)(bpz1 + ko));                          \
        CPCOMMIT();                                                          \
    }

    LOADCH(0, 0);

    int lrow = lane & 15;
    int lcol8 = (lane >> 4) * 8;
    uint32_t a_lm = a_base + (warp_m * 32 + lrow) * (ASTRIDE * 2) + lcol8 * 2;
    uint32_t b_lm = b_base + (warp_n * 64 + lrow) * (ASTRIDE * 2) + lcol8 * 2;

#pragma unroll 1
    for (int c = 0; c < NCH; ++c) {
        int p = c & 1;
        if (c + 1 < NCH) {
            LOADCH(c + 1, 1 - p);
            CPWAIT(1);
        } else {
            CPWAIT(0);
        }
        __syncthreads();
        uint32_t so = p * STAGE_BYTES;
#pragma unroll
        for (int ks = 0; ks < 2; ks++) {
            unsigned af[2][4];
#pragma unroll
            for (int mt = 0; mt < 2; mt++)
                LDSM4(af[mt][0], af[mt][1], af[mt][2], af[mt][3],
                      a_lm + so + mt * 16 * (ASTRIDE * 2) + ks * 32);
            unsigned bf[4][4];
#pragma unroll
            for (int np = 0; np < 4; np++)
                LDSM4(bf[np][0], bf[np][1], bf[np][2], bf[np][3],
                      b_lm + so + np * 16 * (ASTRIDE * 2) + ks * 32);
#pragma unroll
            for (int mt = 0; mt < 2; mt++)
#pragma unroll
                for (int ntile = 0; ntile < 8; ntile++)
                    mma16816(acc[mt][ntile], af[mt],
                             bf[ntile >> 1][ntile & 1],
                             bf[ntile >> 1][(ntile & 1) + 2]);
        }
        __syncthreads();
    }

    // epilogue: d = zsq + bsq - 2*cross
    int rbase = row0 + warp_m * 32;
    int cbase = n0 + warp_n * 64;
    int rlo = rbase + (lane >> 2);
    int csub = (lane & 3) * 2;
#pragma unroll
    for (int mt = 0; mt < 2; mt++) {
        int r0 = rlo + mt * 16;
        int r1 = r0 + 8;
        float zs0 = g_zsq[r0], zs1 = g_zsq[r1];
        float* dp0 = g_d + (size_t)r0 * DSTRIDE;
        float* dp1 = g_d + (size_t)r1 * DSTRIDE;
#pragma unroll
        for (int ntile = 0; ntile < 8; ntile++) {
            int col = cbase + ntile * 8 + csub;
            float b0 = g_bsq[col], b1 = g_bsq[col + 1];
            float2 v0, v1;
            v0.x = (zs0 + b0) - 2.0f * acc[mt][ntile][0];
            v0.y = (zs0 + b1) - 2.0f * acc[mt][ntile][1];
            v1.x = (zs1 + b0) - 2.0f * acc[mt][ntile][2];
            v1.y = (zs1 + b1) - 2.0f * acc[mt][ntile][3];
            *(float2*)(dp0 + col) = v0;
            *(float2*)(dp1 + col) = v1;
        }
    }
#undef LOADCH
}

// ---------------------------------------------------------------------------
// cp.async-pipelined sequential scan. Speculative end-of-iteration LDS preload
// + adjusted slot bases keep the per-step chain short.
// ---------------------------------------------------------------------------
__global__ void k_scan2() {
    __shared__ __align__(16) float buf[16][SD * SW + 4];   // 48B slots, 304B rows
    __shared__ int bb[16][SD];                             // adjusted bases
    int b = threadIdx.x;
    if (b >= 16) return;

    int ia = g_ind[b * T_];
    float coe = 0.0f;
    const float PC = 0.1f / 1024.0f;

    int ab0 = ia & ~3;
    // prologue: rows t = 1..SD into slots t % SD
#pragma unroll
    for (int p = 1; p <= SD; ++p) {
        int slot = p % SD;
        const char* src = (const char*)(g_d + (size_t)(b * T_ + p) * DSTRIDE + ab0);
        int dst = (int)smem_u32(&buf[b][slot * SW]);
        CP16((uint32_t)dst, src);
        CP16((uint32_t)dst + 16, src + 16);
        CP16((uint32_t)dst + 32, src + 32);
        bb[b][slot] = dst - ab0 * 4;
        CPCOMMIT();
    }
    CPWAIT(SD - 1);               // slot for t=1 resident

    int slot = 1;
    int aN = bb[b][1];
    float qh = lds_f(aN + ia * 4);
    float qn = lds_f(aN + min(ia + 1, NE_ - 1) * 4);

    int ibb = b * T_;
    for (int t = 1; t < T_; ++t) {
        int nslot = (slot + 1 == SD) ? 0 : slot + 1;
        int aN2 = lds_i((int)smem_u32(&bb[b][nslot]));   // early, decision-independent

        bool stay = (qh <= qn - coe);
        int ib = min(ia + 1, NE_ - 1);
        ia  = stay ? ia : ib;
        coe = stay ? coe + PC : 0.0f;
        g_ind[ibb + t] = ia;

        int ts = t + SD;
        if (ts < T_) {
            int ab = ia & ~3;
            const char* src = (const char*)(g_d + (size_t)(ibb + ts) * DSTRIDE + ab);
            int dst = (int)smem_u32(&buf[b][slot * SW]);
            CP16((uint32_t)dst, src);
            CP16((uint32_t)dst + 16, src + 16);
            CP16((uint32_t)dst + 32, src + 32);
            bb[b][slot] = dst - ab * 4;
        }
        CPCOMMIT();
        CPWAIT(SD - 1);           // slot for t+1 resident
        qh = lds_f(aN2 + ia * 4);
        qn = lds_f(aN2 + min(ia + 1, NE_ - 1) * 4);
        slot = nslot;
    }
}

// ---------------------------------------------------------------------------
// k_post: gather z_q + indices + li, relu-sum loss over d rows (cols 0..1023)
// plus inline column 1024 (dot with book row 1024).
// ---------------------------------------------------------------------------
__global__ void __launch_bounds__(256) k_post(const float* __restrict__ z,
                                              const float* __restrict__ w,
                                              float* __restrict__ out,
                                              long long out_size) {
    __shared__ double wpart[8];
    int warp = threadIdx.x >> 5;
    int lane = threadIdx.x & 31;
    int row = blockIdx.x * 8 + warp;

    int idx = g_ind[row];
    const float* br = w + (size_t)idx * E_;
    const float* zrow = z + (size_t)row * E_;
    const float* wl = w + (size_t)NE_ * E_;      // book row 1024
    bool wz = (out_size >= (long long)ZQ_SIZE);

    float li = 0.0f, dq = 0.0f;
#pragma unroll
    for (int h = 0; h < 2; h++) {
        int off = h * 128 + 4 * lane;
        float4 q  = *(const float4*)(br + off);
        float4 zv = *(const float4*)(zrow + off);
        float4 wv = *(const float4*)(wl + off);
        float4 o;
        o.x = zv.x + (q.x - zv.x);
        o.y = zv.y + (q.y - zv.y);
        o.z = zv.z + (q.z - zv.z);
        o.w = zv.w + (q.w - zv.w);
        float dx = zv.x - q.x; li += dx * dx;
        dx = zv.y - q.y; li += dx * dx;
        dx = zv.z - q.z; li += dx * dx;
        dx = zv.w - q.w; li += dx * dx;
        dq += zv.x * wv.x + zv.y * wv.y + zv.z * wv.z + zv.w * wv.w;
        if (wz) *(float4*)(out + (size_t)row * E_ + off) = o;
    }
    li = warp_sum(li);
    dq = warp_sum(dq);
    li = __shfl_sync(0xffffffffu, li, 0);
    if (lane == 0 && out_size >= (long long)(IND_OFF + BT_))
        out[IND_OFF + row] = (float)idx;

    const float EPS_ = 1e-6f / 1024.0f;
    const float* drow = g_d + (size_t)row * DSTRIDE;
    float s = 0.0f;
#pragma unroll
    for (int m = 0; m < 8; m++) {
        float4 dv = *(const float4*)(drow + m * 128 + 4 * lane);
        s += fmaxf((li - dv.x) + EPS_, 0.0f);
        s += fmaxf((li - dv.y) + EPS_, 0.0f);
        s += fmaxf((li - dv.z) + EPS_, 0.0f);
        s += fmaxf((li - dv.w) + EPS_, 0.0f);
    }
    if (lane == 0) {
        float d1024 = (g_zsq[row] + g_bsq[NE_]) - 2.0f * dq;
        s += fmaxf((li - d1024) + EPS_, 0.0f);
    }
    s = warp_sum(s);
    if (lane == 0) wpart[warp] = (double)s;
    __syncthreads();
    if (threadIdx.x == 0) {
        double t = 0.0;
        for (int j = 0; j < 8; j++) t += wpart[j];
        g_part[blockIdx.x] = t;
    }
}

// ---------------------------------------------------------------------------
__global__ void k_final(float* __restrict__ out, long long out_size) {
    __shared__ double sd[256];
    __shared__ int smn[256], smx[256];
    int tid = threadIdx.x;
    double s = 0.0;
    for (int i = tid; i < NPOST; i += 256) s += g_part[i];
    int mn = 0x7fffffff, mx = -0x7fffffff;
    for (int i = tid; i < BT_; i += 256) {
        int v = g_ind[i];
        mn = min(mn, v);
        mx = max(mx, v);
    }
    sd[tid] = s; smn[tid] = mn; smx[tid] = mx;
    __syncthreads();
    for (int st = 128; st > 0; st >>= 1) {
        if (tid < st) {
            sd[tid] += sd[tid + st];
            smn[tid] = min(smn[tid], smn[tid + st]);
            smx[tid] = max(smx[tid], smx[tid + st]);
        }
        __syncthreads();
    }
    if (tid == 0) {
        float m = (float)(sd[0] / ((double)BT_ * (double)NB_));
        float loss = 0.25f * m + m;
        if (out_size > (long long)LOSS_OFF) out[LOSS_OFF] = loss;
        if (out_size > (long long)V_OFF)    out[V_OFF] = (float)(smx[0] - smn[0]);
    }
}

// ---------------------------------------------------------------------------
extern "C" void kernel_launch(void* const* d_in, const int* in_sizes, int n_in,
                              void* d_out, int out_size) {
    const float* z = (const float*)d_in[0];
    const float* w = (const float*)d_in[1];
    if (n_in >= 2 && in_sizes[0] == NB_ * E_ && in_sizes[1] == BT_ * E_) {
        const float* tmp = z; z = w; w = tmp;
    }
    float* out = (float*)d_out;
    long long osz = (long long)out_size;

    k_prep<<<(BT_ + NB_ + 7) / 8, 256>>>(z, w);
    k_first<<<B_, 256>>>(z, w);
    k_gemm<<<NGEMM, 256>>>();
    k_scan2<<<1, 32>>>();
    k_post<<<NPOST, 256>>>(z, w, out, osz);
    k_final<<<1, 256>>>(out, osz);
}

// round 9
// speedup vs baseline: 1.3485x; 1.0443x over previous
#include <cuda_runtime.h>
#include <cuda_fp16.h>
#include <cstdint>

#define B_   16
#define T_   1024
#define E_   256
#define NB_  1025
#define BT_  16384
#define NE_  1024

#define ZQ_SIZE  (BT_ * E_)
#define LOSS_OFF ZQ_SIZE
#define IND_OFF  (ZQ_SIZE + 1)
#define V_OFF    (IND_OFF + BT_)

#define DSTRIDE  1024
#define NTILES_N 8               // 8 * 128 = 1024 cols (col 1024 handled in k_post)
#define NTILES_R 128             // 128 * 128 = 16384 rows
#define NGEMM    (NTILES_N * NTILES_R)
#define NPOST    2048

#define K_EXT    768             // 3 products x K=256 (fp16 split)
#define KCH      32
#define NCH      (K_EXT / KCH)   // 24
#define ASTRIDE  40              // half elements per smem row (80 B)

#define SD 8                     // scan pipeline depth (slots)
#define SW 16                    // floats per slot (64 B)

typedef unsigned long long ull;

__device__ int    g_ind[BT_];
__device__ float  g_zsq[BT_];
__device__ float  g_bsq[1152];
__device__ float  g_d[(size_t)BT_ * DSTRIDE];   // 64 MB
__device__ double g_part[NPOST];
__device__ __half a_ext[(size_t)BT_ * K_EXT];   // 24 MB
__device__ __half b_ext[(size_t)NB_ * K_EXT];   // 1.5 MB

static __device__ __forceinline__ float warp_sum(float v) {
#pragma unroll
    for (int o = 16; o > 0; o >>= 1) v += __shfl_xor_sync(0xffffffffu, v, o);
    return v;
}

static __device__ __forceinline__ uint32_t smem_u32(const void* p) {
    uint32_t a;
    asm("{ .reg .u64 t; cvta.to.shared.u64 t, %1; cvt.u32.u64 %0, t; }"
        : "=r"(a) : "l"(p));
    return a;
}

#define CP16(dst, src) \
    asm volatile("cp.async.cg.shared.global [%0], [%1], 16;" :: "r"(dst), "l"(src))
#define CPCOMMIT() asm volatile("cp.async.commit_group;" ::: "memory")
#define CPWAIT(N)  asm volatile("cp.async.wait_group %0;" :: "n"(N) : "memory")

#define LDSM4(r0, r1, r2, r3, addr) \
    asm volatile("ldmatrix.sync.aligned.m8n8.x4.shared.b16 {%0,%1,%2,%3}, [%4];" \
                 : "=r"(r0), "=r"(r1), "=r"(r2), "=r"(r3) : "r"(addr))

static __device__ __forceinline__ void mma16816(float* c, const unsigned* a,
                                                unsigned b0, unsigned b1) {
    asm volatile(
        "mma.sync.aligned.m16n8k16.row.col.f32.f16.f16.f32 "
        "{%0,%1,%2,%3}, {%4,%5,%6,%7}, {%8,%9}, {%0,%1,%2,%3};"
        : "+f"(c[0]), "+f"(c[1]), "+f"(c[2]), "+f"(c[3])
        : "r"(a[0]), "r"(a[1]), "r"(a[2]), "r"(a[3]), "r"(b0), "r"(b1));
}

// ---------------------------------------------------------------------------
// k_prep: fused row norms + fp16 2-way split.
// A_ext segs: [z0, z0, z1]; B_ext segs: [w0, w1, w0]
// ---------------------------------------------------------------------------
__global__ void k_prep(const float* __restrict__ z, const float* __restrict__ w) {
    int gw = (blockIdx.x * blockDim.x + threadIdx.x) >> 5;
    int lane = threadIdx.x & 31;
    if (gw >= BT_ + NB_) return;

    const float* src = (gw < BT_) ? (z + (size_t)gw * E_ + lane * 8)
                                  : (w + (size_t)(gw - BT_) * E_ + lane * 8);
    float4 a = *(const float4*)src;
    float4 b = *(const float4*)(src + 4);
    float f[8] = {a.x, a.y, a.z, a.w, b.x, b.y, b.z, b.w};

    float s = 0.0f;
    union { __half h[8]; uint4 v; } hi, lo;
#pragma unroll
    for (int j = 0; j < 8; j++) {
        s += f[j] * f[j];
        __half h = __float2half_rn(f[j]);
        hi.h[j] = h;
        lo.h[j] = __float2half_rn(f[j] - __half2float(h));
    }
    s = warp_sum(s);

    if (gw < BT_) {
        __half* base = a_ext + (size_t)gw * K_EXT + lane * 8;
        *(uint4*)(base)       = hi.v;
        *(uint4*)(base + 256) = hi.v;
        *(uint4*)(base + 512) = lo.v;
        if (lane == 0) g_zsq[gw] = s;
    } else {
        __half* base = b_ext + (size_t)(gw - BT_) * K_EXT + lane * 8;
        *(uint4*)(base)       = hi.v;
        *(uint4*)(base + 256) = lo.v;
        *(uint4*)(base + 512) = hi.v;
        if (lane == 0) g_bsq[gw - BT_] = s;
    }
}

// ---------------------------------------------------------------------------
// argmin over d[b,0,:]
// ---------------------------------------------------------------------------
__global__ void k_first(const float* __restrict__ z, const float* __restrict__ w) {
    int b = blockIdx.x;
    __shared__ __align__(16) float zs[E_];
    __shared__ float sd[8];
    __shared__ int   sn[8];
    int tid = threadIdx.x;
    zs[tid] = z[(size_t)b * T_ * E_ + tid];
    __syncthreads();

    float zsq0 = g_zsq[b * T_];
    int warp = tid >> 5, lane = tid & 31;
    float4 za = *(const float4*)(zs + 4 * lane);
    float4 zb = *(const float4*)(zs + 128 + 4 * lane);

    float best = 3.4e38f;
    int bestn = 0x7fffffff;
    for (int n = warp; n < NB_; n += 8) {
        const float* wr = w + (size_t)n * E_;
        float4 wa = *(const float4*)(wr + 4 * lane);
        float4 wb = *(const float4*)(wr + 128 + 4 * lane);
        float p = za.x * wa.x + za.y * wa.y + za.z * wa.z + za.w * wa.w
                + zb.x * wb.x + zb.y * wb.y + zb.z * wb.z + zb.w * wb.w;
        p = warp_sum(p);
        float d = (zsq0 + g_bsq[n]) - 2.0f * p;
        if (d < best || (d == best && n < bestn)) { best = d; bestn = n; }
    }
    if (lane == 0) { sd[warp] = best; sn[warp] = bestn; }
    __syncthreads();
    if (tid == 0) {
        float bd = sd[0]; int bn = sn[0];
        for (int j = 1; j < 8; j++)
            if (sd[j] < bd || (sd[j] == bd && sn[j] < bn)) { bd = sd[j]; bn = sn[j]; }
        g_ind[b * T_] = min(bn, NE_ - 1);
    }
}

// ---------------------------------------------------------------------------
// fp16 split-GEMM via mma.sync (m16n8k16). CTA 128x128, K_ext=768, kchunk 32,
// double-buffered cp.async. N = 1024 (col 1024 handled in k_post).
// ---------------------------------------------------------------------------
__global__ void __launch_bounds__(256) k_gemm() {
    __shared__ __align__(16) __half As[2][128][ASTRIDE];
    __shared__ __align__(16) __half Bs[2][128][ASTRIDE];

    int tid = threadIdx.x;
    int wid = tid >> 5;
    int lane = tid & 31;
    int warp_m = wid & 3;       // 0..3  -> 32-row slice
    int warp_n = wid >> 2;      // 0..1  -> 64-col slice

    int bid = blockIdx.x;
    int nt0 = bid % NTILES_N;
    int rt  = bid / NTILES_N;
    int row0 = rt * 128;
    int n0   = nt0 * 128;

    float acc[2][8][4];
#pragma unroll
    for (int i = 0; i < 2; i++)
#pragma unroll
        for (int j = 0; j < 8; j++)
#pragma unroll
            for (int k = 0; k < 4; k++) acc[i][j][k] = 0.0f;

    uint32_t a_base = smem_u32(&As[0][0][0]);
    uint32_t b_base = smem_u32(&Bs[0][0][0]);
    const uint32_t STAGE_BYTES = 128 * ASTRIDE * 2;

    int ch0 = tid * 2, ch1 = tid * 2 + 1;
    int ar0 = ch0 >> 2, as0 = ch0 & 3;
    int ar1 = ch1 >> 2, as1 = ch1 & 3;
    const __half* apz  = a_ext + (size_t)(row0 + ar0) * K_EXT + as0 * 8;
    const __half* apz1 = a_ext + (size_t)(row0 + ar1) * K_EXT + as1 * 8;
    const __half* bpz  = b_ext + (size_t)(n0 + ar0) * K_EXT + as0 * 8;
    const __half* bpz1 = b_ext + (size_t)(n0 + ar1) * K_EXT + as1 * 8;
    uint32_t adst0 = a_base + ar0 * (ASTRIDE * 2) + as0 * 16;
    uint32_t adst1 = a_base + ar1 * (ASTRIDE * 2) + as1 * 16;
    uint32_t bdst0 = b_base + ar0 * (ASTRIDE * 2) + as0 * 16;
    uint32_t bdst1 = b_base + ar1 * (ASTRIDE * 2) + as1 * 16;

#define LOADCH(c, buf)                                                       \
    {                                                                        \
        uint32_t so = (buf) * STAGE_BYTES;                                   \
        int ko = (c) * KCH;                                                  \
        CP16(adst0 + so, (const char*)(apz + ko));                           \
        CP16(adst1 + so, (const char*)(apz1 + ko));                          \
        CP16(bdst0 + so, (const char*)(bpz + ko));                           \
        CP16(bdst1 + so, (const char*)(bpz1 + ko));                          \
        CPCOMMIT();                                                          \
    }

    LOADCH(0, 0);

    int lrow = lane & 15;
    int lcol8 = (lane >> 4) * 8;
    uint32_t a_lm = a_base + (warp_m * 32 + lrow) * (ASTRIDE * 2) + lcol8 * 2;
    uint32_t b_lm = b_base + (warp_n * 64 + lrow) * (ASTRIDE * 2) + lcol8 * 2;

#pragma unroll 1
    for (int c = 0; c < NCH; ++c) {
        int p = c & 1;
        if (c + 1 < NCH) {
            LOADCH(c + 1, 1 - p);
            CPWAIT(1);
        } else {
            CPWAIT(0);
        }
        __syncthreads();
        uint32_t so = p * STAGE_BYTES;
#pragma unroll
        for (int ks = 0; ks < 2; ks++) {
            unsigned af[2][4];
#pragma unroll
            for (int mt = 0; mt < 2; mt++)
                LDSM4(af[mt][0], af[mt][1], af[mt][2], af[mt][3],
                      a_lm + so + mt * 16 * (ASTRIDE * 2) + ks * 32);
            unsigned bf[4][4];
#pragma unroll
            for (int np = 0; np < 4; np++)
                LDSM4(bf[np][0], bf[np][1], bf[np][2], bf[np][3],
                      b_lm + so + np * 16 * (ASTRIDE * 2) + ks * 32);
#pragma unroll
            for (int mt = 0; mt < 2; mt++)
#pragma unroll
                for (int ntile = 0; ntile < 8; ntile++)
                    mma16816(acc[mt][ntile], af[mt],
                             bf[ntile >> 1][ntile & 1],
                             bf[ntile >> 1][(ntile & 1) + 2]);
        }
        __syncthreads();
    }

    // epilogue: d = zsq + bsq - 2*cross
    int rbase = row0 + warp_m * 32;
    int cbase = n0 + warp_n * 64;
    int rlo = rbase + (lane >> 2);
    int csub = (lane & 3) * 2;
#pragma unroll
    for (int mt = 0; mt < 2; mt++) {
        int r0 = rlo + mt * 16;
        int r1 = r0 + 8;
        float zs0 = g_zsq[r0], zs1 = g_zsq[r1];
        float* dp0 = g_d + (size_t)r0 * DSTRIDE;
        float* dp1 = g_d + (size_t)r1 * DSTRIDE;
#pragma unroll
        for (int ntile = 0; ntile < 8; ntile++) {
            int col = cbase + ntile * 8 + csub;
            float b0 = g_bsq[col], b1 = g_bsq[col + 1];
            float2 v0, v1;
            v0.x = (zs0 + b0) - 2.0f * acc[mt][ntile][0];
            v0.y = (zs0 + b1) - 2.0f * acc[mt][ntile][1];
            v1.x = (zs1 + b0) - 2.0f * acc[mt][ntile][2];
            v1.y = (zs1 + b1) - 2.0f * acc[mt][ntile][3];
            *(float2*)(dp0 + col) = v0;
            *(float2*)(dp1 + col) = v1;
        }
    }
#undef LOADCH
}

// ---------------------------------------------------------------------------
// k_scan3: one block per batch. Lanes 0..3 prefetch the 64B window of row
// t+SD via a single cp.async each; ALL lanes redundantly run the decision
// (smem broadcast loads). Slot bases live in registers via 8x unroll.
// ---------------------------------------------------------------------------
__global__ void __launch_bounds__(32) k_scan3() {
    __shared__ __align__(16) float buf[SD][SW];
    int b = blockIdx.x;
    int lane = threadIdx.x;
    int ibb = b * T_;

    int ia = g_ind[ibb];
    float coe = 0.0f;
    const float PC = 0.1f / 1024.0f;

    uint32_t sbase = smem_u32(&buf[0][0]);
    int bases[SD];

    // prologue: slot s <- row t = s+1, window based at ia0 & ~3
    int ab0 = ia & ~3;
#pragma unroll
    for (int s = 0; s < SD; ++s) {
        const char* src = (const char*)(g_d + (size_t)(ibb + s + 1) * DSTRIDE + ab0)
                        + lane * 16;
        if (lane < 4) CP16(sbase + s * 64 + lane * 16, src);
        bases[s] = ab0;
        CPCOMMIT();
    }

    int t = 1;
#pragma unroll 1
    for (int blk = 0; blk < (T_ - 1 + SD - 1) / SD; ++blk) {
#pragma unroll
        for (int s = 0; s < SD; ++s) {
            if (t < T_) {
                CPWAIT(SD - 1);                  // slot s resident
                int off = ia - bases[s];
                int ib2 = min(ia + 1, NE_ - 1);
                float qh = buf[s][off];
                float qn = buf[s][ib2 - bases[s]];
                bool stay = (qh <= qn - coe);
                ia  = stay ? ia : ib2;
                coe = stay ? coe + PC : 0.0f;
                if (lane == 0) g_ind[ibb + t] = ia;
                int ts = t + SD;
                if (ts < T_) {
                    int ab = ia & ~3;
                    const char* src =
                        (const char*)(g_d + (size_t)(ibb + ts) * DSTRIDE + ab)
                        + lane * 16;
                    if (lane < 4) CP16(sbase + s * 64 + lane * 16, src);
                    bases[s] = ab;
                }
                CPCOMMIT();                      // uniform group accounting
                t++;
            }
        }
    }
}

// ---------------------------------------------------------------------------
// k_post: gather z_q + indices + li, relu-sum loss over d rows (cols 0..1023)
// plus inline column 1024 (dot with book row 1024).
// ---------------------------------------------------------------------------
__global__ void __launch_bounds__(256) k_post(const float* __restrict__ z,
                                              const float* __restrict__ w,
                                              float* __restrict__ out,
                                              long long out_size) {
    __shared__ double wpart[8];
    int warp = threadIdx.x >> 5;
    int lane = threadIdx.x & 31;
    int row = blockIdx.x * 8 + warp;

    int idx = g_ind[row];
    const float* br = w + (size_t)idx * E_;
    const float* zrow = z + (size_t)row * E_;
    const float* wl = w + (size_t)NE_ * E_;      // book row 1024
    bool wz = (out_size >= (long long)ZQ_SIZE);

    float li = 0.0f, dq = 0.0f;
#pragma unroll
    for (int h = 0; h < 2; h++) {
        int off = h * 128 + 4 * lane;
        float4 q  = *(const float4*)(br + off);
        float4 zv = *(const float4*)(zrow + off);
        float4 wv = *(const float4*)(wl + off);
        float4 o;
        o.x = zv.x + (q.x - zv.x);
        o.y = zv.y + (q.y - zv.y);
        o.z = zv.z + (q.z - zv.z);
        o.w = zv.w + (q.w - zv.w);
        float dx = zv.x - q.x; li += dx * dx;
        dx = zv.y - q.y; li += dx * dx;
        dx = zv.z - q.z; li += dx * dx;
        dx = zv.w - q.w; li += dx * dx;
        dq += zv.x * wv.x + zv.y * wv.y + zv.z * wv.z + zv.w * wv.w;
        if (wz) *(float4*)(out + (size_t)row * E_ + off) = o;
    }
    li = warp_sum(li);
    dq = warp_sum(dq);
    li = __shfl_sync(0xffffffffu, li, 0);
    if (lane == 0 && out_size >= (long long)(IND_OFF + BT_))
        out[IND_OFF + row] = (float)idx;

    const float EPS_ = 1e-6f / 1024.0f;
    const float* drow = g_d + (size_t)row * DSTRIDE;
    float s = 0.0f;
#pragma unroll
    for (int m = 0; m < 8; m++) {
        float4 dv = *(const float4*)(drow + m * 128 + 4 * lane);
        s += fmaxf((li - dv.x) + EPS_, 0.0f);
        s += fmaxf((li - dv.y) + EPS_, 0.0f);
        s += fmaxf((li - dv.z) + EPS_, 0.0f);
        s += fmaxf((li - dv.w) + EPS_, 0.0f);
    }
    if (lane == 0) {
        float d1024 = (g_zsq[row] + g_bsq[NE_]) - 2.0f * dq;
        s += fmaxf((li - d1024) + EPS_, 0.0f);
    }
    s = warp_sum(s);
    if (lane == 0) wpart[warp] = (double)s;
    __syncthreads();
    if (threadIdx.x == 0) {
        double t = 0.0;
        for (int j = 0; j < 8; j++) t += wpart[j];
        g_part[blockIdx.x] = t;
    }
}

// ---------------------------------------------------------------------------
__global__ void k_final(float* __restrict__ out, long long out_size) {
    __shared__ double sd[256];
    __shared__ int smn[256], smx[256];
    int tid = threadIdx.x;
    double s = 0.0;
    for (int i = tid; i < NPOST; i += 256) s += g_part[i];
    int mn = 0x7fffffff, mx = -0x7fffffff;
    for (int i = tid; i < BT_; i += 256) {
        int v = g_ind[i];
        mn = min(mn, v);
        mx = max(mx, v);
    }
    sd[tid] = s; smn[tid] = mn; smx[tid] = mx;
    __syncthreads();
    for (int st = 128; st > 0; st >>= 1) {
        if (tid < st) {
            sd[tid] += sd[tid + st];
            smn[tid] = min(smn[tid], smn[tid + st]);
            smx[tid] = max(smx[tid], smx[tid + st]);
        }
        __syncthreads();
    }
    if (tid == 0) {
        float m = (float)(sd[0] / ((double)BT_ * (double)NB_));
        float loss = 0.25f * m + m;
        if (out_size > (long long)LOSS_OFF) out[LOSS_OFF] = loss;
        if (out_size > (long long)V_OFF)    out[V_OFF] = (float)(smx[0] - smn[0]);
    }
}

// ---------------------------------------------------------------------------
extern "C" void kernel_launch(void* const* d_in, const int* in_sizes, int n_in,
                              void* d_out, int out_size) {
    const float* z = (const float*)d_in[0];
    const float* w = (const float*)d_in[1];
    if (n_in >= 2 && in_sizes[0] == NB_ * E_ && in_sizes[1] == BT_ * E_) {
        const float* tmp = z; z = w; w = tmp;
    }
    float* out = (float*)d_out;
    long long osz = (long long)out_size;

    k_prep<<<(BT_ + NB_ + 7) / 8, 256>>>(z, w);
    k_first<<<B_, 256>>>(z, w);
    k_gemm<<<NGEMM, 256>>>();
    k_scan3<<<B_, 32>>>();
    k_post<<<NPOST, 256>>>(z, w, out, osz);
    k_final<<<1, 256>>>(out, osz);
}

// round 10
// speedup vs baseline: 1.5275x; 1.1328x over previous
#include <cuda_runtime.h>
#include <cuda_fp16.h>
#include <cstdint>

#define B_   16
#define T_   1024
#define E_   256
#define NB_  1025
#define BT_  16384
#define NE_  1024

#define ZQ_SIZE  (BT_ * E_)
#define LOSS_OFF ZQ_SIZE
#define IND_OFF  (ZQ_SIZE + 1)
#define V_OFF    (IND_OFF + BT_)

#define DSTRIDE  1024
#define NTILES_N 8               // 8 * 128 = 1024 cols (col 1024 handled in k_post)
#define NTILES_R 128             // 128 * 128 = 16384 rows
#define NGEMM    (NTILES_N * NTILES_R)
#define NPOST    2048

#define K_EXT    768             // 3 products x K=256 (fp16 split)
#define KCH      32
#define NCH      (K_EXT / KCH)   // 24
#define ASTRIDE  40              // half elements per smem row (80 B)

typedef unsigned long long ull;

__device__ int    g_ind[BT_];
__device__ int    g_sink[B_];
__device__ float  g_zsq[BT_];
__device__ float  g_bsq[1152];
__device__ float  g_d[(size_t)(BT_ + 16) * DSTRIDE];   // padded 16 rows for scan tail
__device__ double g_part[NPOST];
__device__ __half a_ext[(size_t)BT_ * K_EXT];   // 24 MB
__device__ __half b_ext[(size_t)NB_ * K_EXT];   // 1.5 MB

static __device__ __forceinline__ float warp_sum(float v) {
#pragma unroll
    for (int o = 16; o > 0; o >>= 1) v += __shfl_xor_sync(0xffffffffu, v, o);
    return v;
}

static __device__ __forceinline__ uint32_t smem_u32(const void* p) {
    uint32_t a;
    asm("{ .reg .u64 t; cvta.to.shared.u64 t, %1; cvt.u32.u64 %0, t; }"
        : "=r"(a) : "l"(p));
    return a;
}

static __device__ __forceinline__ float lds_f(uint32_t addr) {
    float v;
    asm volatile("ld.shared.f32 %0, [%1];" : "=f"(v) : "r"(addr));
    return v;
}

#define CP16(dst, src) \
    asm volatile("cp.async.cg.shared.global [%0], [%1], 16;" :: "r"(dst), "l"(src))
#define CP16S(dst, src, sz) \
    asm volatile("cp.async.cg.shared.global [%0], [%1], 16, %2;" :: "r"(dst), "l"(src), "r"(sz))
#define CPCOMMIT() asm volatile("cp.async.commit_group;" ::: "memory")
#define CPWAIT(N)  asm volatile("cp.async.wait_group %0;" :: "n"(N) : "memory")

#define LDSM4(r0, r1, r2, r3, addr) \
    asm volatile("ldmatrix.sync.aligned.m8n8.x4.shared.b16 {%0,%1,%2,%3}, [%4];" \
                 : "=r"(r0), "=r"(r1), "=r"(r2), "=r"(r3) : "r"(addr))

static __device__ __forceinline__ void mma16816(float* c, const unsigned* a,
                                                unsigned b0, unsigned b1) {
    asm volatile(
        "mma.sync.aligned.m16n8k16.row.col.f32.f16.f16.f32 "
        "{%0,%1,%2,%3}, {%4,%5,%6,%7}, {%8,%9}, {%0,%1,%2,%3};"
        : "+f"(c[0]), "+f"(c[1]), "+f"(c[2]), "+f"(c[3])
        : "r"(a[0]), "r"(a[1]), "r"(a[2]), "r"(a[3]), "r"(b0), "r"(b1));
}

// ---------------------------------------------------------------------------
// k_prep: fused row norms + fp16 2-way split.
// A_ext segs: [z0, z0, z1]; B_ext segs: [w0, w1, w0]
// ---------------------------------------------------------------------------
__global__ void k_prep(const float* __restrict__ z, const float* __restrict__ w) {
    int gw = (blockIdx.x * blockDim.x + threadIdx.x) >> 5;
    int lane = threadIdx.x & 31;
    if (gw >= BT_ + NB_) return;

    const float* src = (gw < BT_) ? (z + (size_t)gw * E_ + lane * 8)
                                  : (w + (size_t)(gw - BT_) * E_ + lane * 8);
    float4 a = *(const float4*)src;
    float4 b = *(const float4*)(src + 4);
    float f[8] = {a.x, a.y, a.z, a.w, b.x, b.y, b.z, b.w};

    float s = 0.0f;
    union { __half h[8]; uint4 v; } hi, lo;
#pragma unroll
    for (int j = 0; j < 8; j++) {
        s += f[j] * f[j];
        __half h = __float2half_rn(f[j]);
        hi.h[j] = h;
        lo.h[j] = __float2half_rn(f[j] - __half2float(h));
    }
    s = warp_sum(s);

    if (gw < BT_) {
        __half* base = a_ext + (size_t)gw * K_EXT + lane * 8;
        *(uint4*)(base)       = hi.v;
        *(uint4*)(base + 256) = hi.v;
        *(uint4*)(base + 512) = lo.v;
        if (lane == 0) g_zsq[gw] = s;
    } else {
        __half* base = b_ext + (size_t)(gw - BT_) * K_EXT + lane * 8;
        *(uint4*)(base)       = hi.v;
        *(uint4*)(base + 256) = lo.v;
        *(uint4*)(base + 512) = hi.v;
        if (lane == 0) g_bsq[gw - BT_] = s;
    }
}

// ---------------------------------------------------------------------------
// argmin over d[b,0,:]
// ---------------------------------------------------------------------------
__global__ void k_first(const float* __restrict__ z, const float* __restrict__ w) {
    int b = blockIdx.x;
    __shared__ __align__(16) float zs[E_];
    __shared__ float sd[8];
    __shared__ int   sn[8];
    int tid = threadIdx.x;
    zs[tid] = z[(size_t)b * T_ * E_ + tid];
    __syncthreads();

    float zsq0 = g_zsq[b * T_];
    int warp = tid >> 5, lane = tid & 31;
    float4 za = *(const float4*)(zs + 4 * lane);
    float4 zb = *(const float4*)(zs + 128 + 4 * lane);

    float best = 3.4e38f;
    int bestn = 0x7fffffff;
    for (int n = warp; n < NB_; n += 8) {
        const float* wr = w + (size_t)n * E_;
        float4 wa = *(const float4*)(wr + 4 * lane);
        float4 wb = *(const float4*)(wr + 128 + 4 * lane);
        float p = za.x * wa.x + za.y * wa.y + za.z * wa.z + za.w * wa.w
                + zb.x * wb.x + zb.y * wb.y + zb.z * wb.z + zb.w * wb.w;
        p = warp_sum(p);
        float d = (zsq0 + g_bsq[n]) - 2.0f * p;
        if (d < best || (d == best && n < bestn)) { best = d; bestn = n; }
    }
    if (lane == 0) { sd[warp] = best; sn[warp] = bestn; }
    __syncthreads();
    if (tid == 0) {
        float bd = sd[0]; int bn = sn[0];
        for (int j = 1; j < 8; j++)
            if (sd[j] < bd || (sd[j] == bd && sn[j] < bn)) { bd = sd[j]; bn = sn[j]; }
        g_ind[b * T_] = min(bn, NE_ - 1);
    }
}

// ---------------------------------------------------------------------------
// fp16 split-GEMM via mma.sync (m16n8k16). CTA 128x128, K_ext=768, kchunk 32,
// double-buffered cp.async. N = 1024 (col 1024 handled in k_post).
// ---------------------------------------------------------------------------
__global__ void __launch_bounds__(256) k_gemm() {
    __shared__ __align__(16) __half As[2][128][ASTRIDE];
    __shared__ __align__(16) __half Bs[2][128][ASTRIDE];

    int tid = threadIdx.x;
    int wid = tid >> 5;
    int lane = tid & 31;
    int warp_m = wid & 3;
    int warp_n = wid >> 2;

    int bid = blockIdx.x;
    int nt0 = bid % NTILES_N;
    int rt  = bid / NTILES_N;
    int row0 = rt * 128;
    int n0   = nt0 * 128;

    float acc[2][8][4];
#pragma unroll
    for (int i = 0; i < 2; i++)
#pragma unroll
        for (int j = 0; j < 8; j++)
#pragma unroll
            for (int k = 0; k < 4; k++) acc[i][j][k] = 0.0f;

    uint32_t a_base = smem_u32(&As[0][0][0]);
    uint32_t b_base = smem_u32(&Bs[0][0][0]);
    const uint32_t STAGE_BYTES = 128 * ASTRIDE * 2;

    int ch0 = tid * 2, ch1 = tid * 2 + 1;
    int ar0 = ch0 >> 2, as0 = ch0 & 3;
    int ar1 = ch1 >> 2, as1 = ch1 & 3;
    const __half* apz  = a_ext + (size_t)(row0 + ar0) * K_EXT + as0 * 8;
    const __half* apz1 = a_ext + (size_t)(row0 + ar1) * K_EXT + as1 * 8;
    const __half* bpz  = b_ext + (size_t)(n0 + ar0) * K_EXT + as0 * 8;
    const __half* bpz1 = b_ext + (size_t)(n0 + ar1) * K_EXT + as1 * 8;
    uint32_t adst0 = a_base + ar0 * (ASTRIDE * 2) + as0 * 16;
    uint32_t adst1 = a_base + ar1 * (ASTRIDE * 2) + as1 * 16;
    uint32_t bdst0 = b_base + ar0 * (ASTRIDE * 2) + as0 * 16;
    uint32_t bdst1 = b_base + ar1 * (ASTRIDE * 2) + as1 * 16;

#define LOADCH(c, buf)                                                       \
    {                                                                        \
        uint32_t so = (buf) * STAGE_BYTES;                                   \
        int ko = (c) * KCH;                                                  \
        CP16(adst0 + so, (const char*)(apz + ko));                           \
        CP16(adst1 + so, (const char*)(apz1 + ko));                          \
        CP16(bdst0 + so, (const char*)(bpz + ko));                           \
        CP16(bdst1 + so, (const char*)(bpz1 + ko));                          \
        CPCOMMIT();                                                          \
    }

    LOADCH(0, 0);

    int lrow = lane & 15;
    int lcol8 = (lane >> 4) * 8;
    uint32_t a_lm = a_base + (warp_m * 32 + lrow) * (ASTRIDE * 2) + lcol8 * 2;
    uint32_t b_lm = b_base + (warp_n * 64 + lrow) * (ASTRIDE * 2) + lcol8 * 2;

#pragma unroll 1
    for (int c = 0; c < NCH; ++c) {
        int p = c & 1;
        if (c + 1 < NCH) {
            LOADCH(c + 1, 1 - p);
            CPWAIT(1);
        } else {
            CPWAIT(0);
        }
        __syncthreads();
        uint32_t so = p * STAGE_BYTES;
#pragma unroll
        for (int ks = 0; ks < 2; ks++) {
            unsigned af[2][4];
#pragma unroll
            for (int mt = 0; mt < 2; mt++)
                LDSM4(af[mt][0], af[mt][1], af[mt][2], af[mt][3],
                      a_lm + so + mt * 16 * (ASTRIDE * 2) + ks * 32);
            unsigned bf[4][4];
#pragma unroll
            for (int np = 0; np < 4; np++)
                LDSM4(bf[np][0], bf[np][1], bf[np][2], bf[np][3],
                      b_lm + so + np * 16 * (ASTRIDE * 2) + ks * 32);
#pragma unroll
            for (int mt = 0; mt < 2; mt++)
#pragma unroll
                for (int ntile = 0; ntile < 8; ntile++)
                    mma16816(acc[mt][ntile], af[mt],
                             bf[ntile >> 1][ntile & 1],
                             bf[ntile >> 1][(ntile & 1) + 2]);
        }
        __syncthreads();
    }

    // epilogue: d = zsq + bsq - 2*cross
    int rbase = row0 + warp_m * 32;
    int cbase = n0 + warp_n * 64;
    int rlo = rbase + (lane >> 2);
    int csub = (lane & 3) * 2;
#pragma unroll
    for (int mt = 0; mt < 2; mt++) {
        int r0 = rlo + mt * 16;
        int r1 = r0 + 8;
        float zs0 = g_zsq[r0], zs1 = g_zsq[r1];
        float* dp0 = g_d + (size_t)r0 * DSTRIDE;
        float* dp1 = g_d + (size_t)r1 * DSTRIDE;
#pragma unroll
        for (int ntile = 0; ntile < 8; ntile++) {
            int col = cbase + ntile * 8 + csub;
            float b0 = g_bsq[col], b1 = g_bsq[col + 1];
            float2 v0, v1;
            v0.x = (zs0 + b0) - 2.0f * acc[mt][ntile][0];
            v0.y = (zs0 + b1) - 2.0f * acc[mt][ntile][1];
            v1.x = (zs1 + b0) - 2.0f * acc[mt][ntile][2];
            v1.y = (zs1 + b1) - 2.0f * acc[mt][ntile][3];
            *(float2*)(dp0 + col) = v0;
            *(float2*)(dp1 + col) = v1;
        }
    }
#undef LOADCH
}

// ---------------------------------------------------------------------------
// k_scan4: branchless grouped scan. One block per batch.
// Groups of 4 steps share one CPWAIT/CPCOMMIT; 3 groups in flight.
// Window = 4 rows x 80 B (20 floats) per slot; 20 active prefetch lanes.
// Slot bases and smem addresses live in rotating registers.
// ---------------------------------------------------------------------------
__global__ void __launch_bounds__(32) k_scan4() {
    __shared__ __align__(16) char sbuf[1664];   // 3 slots * 320 B + scratch
    int b = blockIdx.x;
    int lane = threadIdx.x;
    int ibb = b * T_;

    int ia = g_ind[ibb];
    float coe = 0.0f;
    const float PC = 0.1f / 1024.0f;

    uint32_t sbase = smem_u32(sbuf);

    // lane mapping for prefetch: lanes 0..19 -> (row, 16B-chunk); others inert
    int act = lane < 20;
    int prow = act ? (lane / 5) : 0;
    int pchk = act ? (lane % 5) : 0;
    uint32_t dstoff = act ? (uint32_t)(prow * 80 + pchk * 16) : 960u;
    uint32_t psz = act ? 16u : 0u;
    const char* sp = (const char*)(g_d + (size_t)(ibb + 1 + prow) * DSTRIDE)
                   + pchk * 16;
    const size_t GSTRIDE = (size_t)4 * DSTRIDE * 4;   // 4 rows in bytes

    // prologue: 3 groups (rows 1..12) based at ia0 & ~3
    int ab0 = ia & ~3;
#pragma unroll
    for (int s = 0; s < 3; ++s) {
        CP16S(sbase + s * 320 + dstoff, sp + (size_t)ab0 * 4, psz);
        CPCOMMIT();
        sp += GSTRIDE;
    }

    uint32_t s0 = sbase, s1 = sbase + 320, s2 = sbase + 640;
    int b0 = ab0, b1 = ab0, b2 = ab0;
    int* gout = g_ind + ibb;
    int* sink = &g_sink[b];
    int t = 1;

#pragma unroll 1
    for (int g = 0; g < 256; ++g) {
        CPWAIT(2);                       // oldest group resident
        uint32_t adj = s0 - (uint32_t)(b0 * 4);
#pragma unroll
        for (int j = 0; j < 4; ++j) {
            float qh = lds_f(adj + j * 80 + ia * 4);
            int ib2 = min(ia + 1, NE_ - 1);
            float qn = lds_f(adj + j * 80 + ib2 * 4);
            bool stay = (qh <= qn - coe);
            ia  = stay ? ia : ib2;
            coe = stay ? coe + PC : 0.0f;
            int* addr = (t + j <= T_ - 1) ? (gout + t + j) : sink;
            *addr = ia;
        }
        t += 4;
        int ab = ia & ~3;
        CP16S(s0 + dstoff, sp + (size_t)ab * 4, psz);
        CPCOMMIT();
        sp += GSTRIDE;
        uint32_t st = s0; s0 = s1; s1 = s2; s2 = st;
        b0 = b1; b1 = b2; b2 = ab;
    }
}

// ---------------------------------------------------------------------------
// k_post: gather z_q + indices + li, relu-sum loss over d rows (cols 0..1023)
// plus inline column 1024 (dot with book row 1024).
// ---------------------------------------------------------------------------
__global__ void __launch_bounds__(256) k_post(const float* __restrict__ z,
                                              const float* __restrict__ w,
                                              float* __restrict__ out,
                                              long long out_size) {
    __shared__ double wpart[8];
    int warp = threadIdx.x >> 5;
    int lane = threadIdx.x & 31;
    int row = blockIdx.x * 8 + warp;

    int idx = g_ind[row];
    const float* br = w + (size_t)idx * E_;
    const float* zrow = z + (size_t)row * E_;
    const float* wl = w + (size_t)NE_ * E_;      // book row 1024
    bool wz = (out_size >= (long long)ZQ_SIZE);

    float li = 0.0f, dq = 0.0f;
#pragma unroll
    for (int h = 0; h < 2; h++) {
        int off = h * 128 + 4 * lane;
        float4 q  = *(const float4*)(br + off);
        float4 zv = *(const float4*)(zrow + off);
        float4 wv = *(const float4*)(wl + off);
        float4 o;
        o.x = zv.x + (q.x - zv.x);
        o.y = zv.y + (q.y - zv.y);
        o.z = zv.z + (q.z - zv.z);
        o.w = zv.w + (q.w - zv.w);
        float dx = zv.x - q.x; li += dx * dx;
        dx = zv.y - q.y; li += dx * dx;
        dx = zv.z - q.z; li += dx * dx;
        dx = zv.w - q.w; li += dx * dx;
        dq += zv.x * wv.x + zv.y * wv.y + zv.z * wv.z + zv.w * wv.w;
        if (wz) *(float4*)(out + (size_t)row * E_ + off) = o;
    }
    li = warp_sum(li);
    dq = warp_sum(dq);
    li = __shfl_sync(0xffffffffu, li, 0);
    if (lane == 0 && out_size >= (long long)(IND_OFF + BT_))
        out[IND_OFF + row] = (float)idx;

    const float EPS_ = 1e-6f / 1024.0f;
    const float* drow = g_d + (size_t)row * DSTRIDE;
    float s = 0.0f;
#pragma unroll
    for (int m = 0; m < 8; m++) {
        float4 dv = *(const float4*)(drow + m * 128 + 4 * lane);
        s += fmaxf((li - dv.x) + EPS_, 0.0f);
        s += fmaxf((li - dv.y) + EPS_, 0.0f);
        s += fmaxf((li - dv.z) + EPS_, 0.0f);
        s += fmaxf((li - dv.w) + EPS_, 0.0f);
    }
    if (lane == 0) {
        float d1024 = (g_zsq[row] + g_bsq[NE_]) - 2.0f * dq;
        s += fmaxf((li - d1024) + EPS_, 0.0f);
    }
    s = warp_sum(s);
    if (lane == 0) wpart[warp] = (double)s;
    __syncthreads();
    if (threadIdx.x == 0) {
        double t = 0.0;
        for (int j = 0; j < 8; j++) t += wpart[j];
        g_part[blockIdx.x] = t;
    }
}

// ---------------------------------------------------------------------------
__global__ void k_final(float* __restrict__ out, long long out_size) {
    __shared__ double sd[256];
    __shared__ int smn[256], smx[256];
    int tid = threadIdx.x;
    double s = 0.0;
    for (int i = tid; i < NPOST; i += 256) s += g_part[i];
    int mn = 0x7fffffff, mx = -0x7fffffff;
    for (int i = tid; i < BT_; i += 256) {
        int v = g_ind[i];
        mn = min(mn, v);
        mx = max(mx, v);
    }
    sd[tid] = s; smn[tid] = mn; smx[tid] = mx;
    __syncthreads();
    for (int st = 128; st > 0; st >>= 1) {
        if (tid < st) {
            sd[tid] += sd[tid + st];
            smn[tid] = min(smn[tid], smn[tid + st]);
            smx[tid] = max(smx[tid], smx[tid + st]);
        }
        __syncthreads();
    }
    if (tid == 0) {
        float m = (float)(sd[0] / ((double)BT_ * (double)NB_));
        float loss = 0.25f * m + m;
        if (out_size > (long long)LOSS_OFF) out[LOSS_OFF] = loss;
        if (out_size > (long long)V_OFF)    out[V_OFF] = (float)(smx[0] - smn[0]);
    }
}

// ---------------------------------------------------------------------------
extern "C" void kernel_launch(void* const* d_in, const int* in_sizes, int n_in,
                              void* d_out, int out_size) {
    const float* z = (const float*)d_in[0];
    const float* w = (const float*)d_in[1];
    if (n_in >= 2 && in_sizes[0] == NB_ * E_ && in_sizes[1] == BT_ * E_) {
        const float* tmp = z; z = w; w = tmp;
    }
    float* out = (float*)d_out;
    long long osz = (long long)out_size;

    k_prep<<<(BT_ + NB_ + 7) / 8, 256>>>(z, w);
    k_first<<<B_, 256>>>(z, w);
    k_gemm<<<NGEMM, 256>>>();
    k_scan4<<<B_, 32>>>();
    k_post<<<NPOST, 256>>>(z, w, out, osz);
    k_final<<<1, 256>>>(out, osz);
}

// round 11
// speedup vs baseline: 1.7669x; 1.1567x over previous
#include <cuda_runtime.h>
#include <cuda_fp16.h>
#include <cstdint>

#define B_   16
#define T_   1024
#define E_   256
#define NB_  1025
#define BT_  16384
#define NE_  1024

#define ZQ_SIZE  (BT_ * E_)
#define LOSS_OFF ZQ_SIZE
#define IND_OFF  (ZQ_SIZE + 1)
#define V_OFF    (IND_OFF + BT_)

#define DSTRIDE  1024
#define NTILES_N 8               // 8 * 128 = 1024 cols (col 1024 handled in k_post)
#define NTILES_R 128             // 128-row chunks, t-chunk-major: rb = tc*16 + b
#define NGEMM    (NTILES_N * NTILES_R)
#define NPOST    2048

#define K_EXT    768             // 3 products x K=256 (fp16 split)
#define KCH      32
#define NCH      (K_EXT / KCH)   // 24
#define ASTRIDE  40              // half elements per smem row (80 B)

typedef unsigned long long ull;

__device__ int    g_ind[BT_];
__device__ int    g_sink[B_];
__device__ float  g_zsq[BT_];
__device__ float  g_bsq[1152];
__device__ float  g_d[(size_t)(BT_ + 16) * DSTRIDE];   // padded rows for scan tail
__device__ double g_part[NPOST];
__device__ int    g_rowflag[NTILES_R];
__device__ __half a_ext[(size_t)BT_ * K_EXT];   // 24 MB
__device__ __half b_ext[(size_t)NB_ * K_EXT];   // 1.5 MB

static __device__ __forceinline__ float warp_sum(float v) {
#pragma unroll
    for (int o = 16; o > 0; o >>= 1) v += __shfl_xor_sync(0xffffffffu, v, o);
    return v;
}

static __device__ __forceinline__ uint32_t smem_u32(const void* p) {
    uint32_t a;
    asm("{ .reg .u64 t; cvta.to.shared.u64 t, %1; cvt.u32.u64 %0, t; }"
        : "=r"(a) : "l"(p));
    return a;
}

static __device__ __forceinline__ int ld_acq(const int* p) {
    int v;
    asm volatile("ld.acquire.gpu.global.s32 %0, [%1];" : "=r"(v) : "l"(p) : "memory");
    return v;
}

#define CP16(dst, src) \
    asm volatile("cp.async.cg.shared.global [%0], [%1], 16;" :: "r"(dst), "l"(src))
#define CPCOMMIT() asm volatile("cp.async.commit_group;" ::: "memory")
#define CPWAIT(N)  asm volatile("cp.async.wait_group %0;" :: "n"(N) : "memory")

#define LDSM4(r0, r1, r2, r3, addr) \
    asm volatile("ldmatrix.sync.aligned.m8n8.x4.shared.b16 {%0,%1,%2,%3}, [%4];" \
                 : "=r"(r0), "=r"(r1), "=r"(r2), "=r"(r3) : "r"(addr))

static __device__ __forceinline__ void mma16816(float* c, const unsigned* a,
                                                unsigned b0, unsigned b1) {
    asm volatile(
        "mma.sync.aligned.m16n8k16.row.col.f32.f16.f16.f32 "
        "{%0,%1,%2,%3}, {%4,%5,%6,%7}, {%8,%9}, {%0,%1,%2,%3};"
        : "+f"(c[0]), "+f"(c[1]), "+f"(c[2]), "+f"(c[3])
        : "r"(a[0]), "r"(a[1]), "r"(a[2]), "r"(a[3]), "r"(b0), "r"(b1));
}

// ---------------------------------------------------------------------------
// k_prep: fused row norms + fp16 2-way split + flag reset.
// A_ext segs: [z0, z0, z1]; B_ext segs: [w0, w1, w0]
// ---------------------------------------------------------------------------
__global__ void k_prep(const float* __restrict__ z, const float* __restrict__ w) {
    if (blockIdx.x == 0 && threadIdx.x < NTILES_R) g_rowflag[threadIdx.x] = 0;
    int gw = (blockIdx.x * blockDim.x + threadIdx.x) >> 5;
    int lane = threadIdx.x & 31;
    if (gw >= BT_ + NB_) return;

    const float* src = (gw < BT_) ? (z + (size_t)gw * E_ + lane * 8)
                                  : (w + (size_t)(gw - BT_) * E_ + lane * 8);
    float4 a = *(const float4*)src;
    float4 b = *(const float4*)(src + 4);
    float f[8] = {a.x, a.y, a.z, a.w, b.x, b.y, b.z, b.w};

    float s = 0.0f;
    union { __half h[8]; uint4 v; } hi, lo;
#pragma unroll
    for (int j = 0; j < 8; j++) {
        s += f[j] * f[j];
        __half h = __float2half_rn(f[j]);
        hi.h[j] = h;
        lo.h[j] = __float2half_rn(f[j] - __half2float(h));
    }
    s = warp_sum(s);

    if (gw < BT_) {
        __half* base = a_ext + (size_t)gw * K_EXT + lane * 8;
        *(uint4*)(base)       = hi.v;
        *(uint4*)(base + 256) = hi.v;
        *(uint4*)(base + 512) = lo.v;
        if (lane == 0) g_zsq[gw] = s;
    } else {
        __half* base = b_ext + (size_t)(gw - BT_) * K_EXT + lane * 8;
        *(uint4*)(base)       = hi.v;
        *(uint4*)(base + 256) = lo.v;
        *(uint4*)(base + 512) = hi.v;
        if (lane == 0) g_bsq[gw - BT_] = s;
    }
}

// ---------------------------------------------------------------------------
// argmin over d[b,0,:]
// ---------------------------------------------------------------------------
__global__ void k_first(const float* __restrict__ z, const float* __restrict__ w) {
    int b = blockIdx.x;
    __shared__ __align__(16) float zs[E_];
    __shared__ float sd[8];
    __shared__ int   sn[8];
    int tid = threadIdx.x;
    zs[tid] = z[(size_t)b * T_ * E_ + tid];
    __syncthreads();

    float zsq0 = g_zsq[b * T_];
    int warp = tid >> 5, lane = tid & 31;
    float4 za = *(const float4*)(zs + 4 * lane);
    float4 zb = *(const float4*)(zs + 128 + 4 * lane);

    float best = 3.4e38f;
    int bestn = 0x7fffffff;
    for (int n = warp; n < NB_; n += 8) {
        const float* wr = w + (size_t)n * E_;
        float4 wa = *(const float4*)(wr + 4 * lane);
        float4 wb = *(const float4*)(wr + 128 + 4 * lane);
        float p = za.x * wa.x + za.y * wa.y + za.z * wa.z + za.w * wa.w
                + zb.x * wb.x + zb.y * wb.y + zb.z * wb.z + zb.w * wb.w;
        p = warp_sum(p);
        float d = (zsq0 + g_bsq[n]) - 2.0f * p;
        if (d < best || (d == best && n < bestn)) { best = d; bestn = n; }
    }
    if (lane == 0) { sd[warp] = best; sn[warp] = bestn; }
    __syncthreads();
    if (tid == 0) {
        float bd = sd[0]; int bn = sn[0];
        for (int j = 1; j < 8; j++)
            if (sd[j] < bd || (sd[j] == bd && sn[j] < bn)) { bd = sd[j]; bn = sn[j]; }
        g_ind[b * T_] = min(bn, NE_ - 1);
    }
}

// ---------------------------------------------------------------------------
// Mega kernel.
// Blocks 0..15: trailing scan (LDG + SHFL.IDX windows, generic-proxy only).
// Blocks 16..16+NGEMM: R10 HMMA split-GEMM, t-chunk-major tiles + flag release.
// ---------------------------------------------------------------------------
__global__ void __launch_bounds__(256) k_mega() {
    __shared__ __align__(16) __half As[2][128][ASTRIDE];
    __shared__ __align__(16) __half Bs[2][128][ASTRIDE];

    int tid = threadIdx.x;

    if (blockIdx.x < 16) {
        // ---------------- scan path ----------------
        if (tid >= 32) return;
        int b = blockIdx.x;
        int lane = tid;
        int ibb = b * T_;
        int ia = g_ind[ibb];
        float coe = 0.0f;
        const float PC = 0.1f / 1024.0f;
        int pl = min(lane, 23);
        int ready_hi = 0;
        int* gout = g_ind + ibb;
        int* sink = &g_sink[b];

#define WAITROW(tt)                                                        \
        while ((tt) >= ready_hi) {                                         \
            int fidx = ((ready_hi >> 7) << 4) + b;                         \
            while (ld_acq(&g_rowflag[fidx]) < NTILES_N) __nanosleep(64);   \
            ready_hi += 128;                                               \
        }

        float wv[4][4];
        int bs0, bs1, bs2, bs3;

        // prologue: 4 groups, rows 1..16, base ia0 & ~3
        WAITROW(16 <= T_ - 1 ? 16 : T_ - 1);
        int ab0 = ia & ~3;
#pragma unroll
        for (int s = 0; s < 4; ++s)
#pragma unroll
            for (int j = 0; j < 4; ++j)
                wv[s][j] = g_d[(size_t)(ibb + 1 + s * 4 + j) * DSTRIDE + ab0 + pl];
        bs0 = ab0; bs1 = ab0; bs2 = ab0; bs3 = ab0;

        int t = 1;
#define PROCG(S, BASEVAR)                                                  \
        {                                                                  \
            int base_ = BASEVAR;                                           \
            _Pragma("unroll")                                              \
            for (int j = 0; j < 4; ++j) {                                  \
                int ib2 = min(ia + 1, NE_ - 1);                            \
                float qh = __shfl_sync(0xffffffffu, wv[S][j], ia - base_); \
                float qn = __shfl_sync(0xffffffffu, wv[S][j], ib2 - base_);\
                bool stay = (qh <= qn - coe);                              \
                ia  = stay ? ia : ib2;                                     \
                coe = stay ? coe + PC : 0.0f;                              \
                if (lane == 0) {                                           \
                    int* a_ = (t + j <= T_ - 1) ? (gout + t + j) : sink;   \
                    *a_ = ia;                                              \
                }                                                          \
            }                                                              \
            t += 4;                                                        \
            int tp = t + 12;                                               \
            if (tp + 3 <= T_) {                                            \
                int wr_ = tp + 3 <= T_ - 1 ? tp + 3 : T_ - 1;              \
                WAITROW(wr_);                                              \
                int ab_ = ia & ~3;                                         \
                _Pragma("unroll")                                          \
                for (int j = 0; j < 4; ++j)                                \
                    wv[S][j] = g_d[(size_t)(ibb + tp + j) * DSTRIDE + ab_ + pl]; \
                BASEVAR = ab_;                                             \
            }                                                              \
        }

#pragma unroll 1
        for (int it = 0; it < 64; ++it) {
            PROCG(0, bs0)
            PROCG(1, bs1)
            PROCG(2, bs2)
            PROCG(3, bs3)
        }
#undef PROCG
#undef WAITROW
        return;
    }

    // ---------------- GEMM path ----------------
    int wid = tid >> 5;
    int lane = tid & 31;
    int warp_m = wid & 3;
    int warp_n = wid >> 2;

    int gi = blockIdx.x - 16;
    int nt0 = gi % NTILES_N;
    int rb  = gi / NTILES_N;                 // rb = tc*16 + b
    int row0 = (rb & 15) * T_ + (rb >> 4) * 128;
    int n0   = nt0 * 128;

    float acc[2][8][4];
#pragma unroll
    for (int i = 0; i < 2; i++)
#pragma unroll
        for (int j = 0; j < 8; j++)
#pragma unroll
            for (int k = 0; k < 4; k++) acc[i][j][k] = 0.0f;

    uint32_t a_base = smem_u32(&As[0][0][0]);
    uint32_t b_base = smem_u32(&Bs[0][0][0]);
    const uint32_t STAGE_BYTES = 128 * ASTRIDE * 2;

    int ch0 = tid * 2, ch1 = tid * 2 + 1;
    int ar0 = ch0 >> 2, as0 = ch0 & 3;
    int ar1 = ch1 >> 2, as1 = ch1 & 3;
    const __half* apz  = a_ext + (size_t)(row0 + ar0) * K_EXT + as0 * 8;
    const __half* apz1 = a_ext + (size_t)(row0 + ar1) * K_EXT + as1 * 8;
    const __half* bpz  = b_ext + (size_t)(n0 + ar0) * K_EXT + as0 * 8;
    const __half* bpz1 = b_ext + (size_t)(n0 + ar1) * K_EXT + as1 * 8;
    uint32_t adst0 = a_base + ar0 * (ASTRIDE * 2) + as0 * 16;
    uint32_t adst1 = a_base + ar1 * (ASTRIDE * 2) + as1 * 16;
    uint32_t bdst0 = b_base + ar0 * (ASTRIDE * 2) + as0 * 16;
    uint32_t bdst1 = b_base + ar1 * (ASTRIDE * 2) + as1 * 16;

#define LOADCH(c, buf)                                                       \
    {                                                                        \
        uint32_t so = (buf) * STAGE_BYTES;                                   \
        int ko = (c) * KCH;                                                  \
        CP16(adst0 + so, (const char*)(apz + ko));                           \
        CP16(adst1 + so, (const char*)(apz1 + ko));                          \
        CP16(bdst0 + so, (const char*)(bpz + ko));                           \
        CP16(bdst1 + so, (const char*)(bpz1 + ko));                          \
        CPCOMMIT();                                                          \
    }

    LOADCH(0, 0);

    int lrow = lane & 15;
    int lcol8 = (lane >> 4) * 8;
    uint32_t a_lm = a_base + (warp_m * 32 + lrow) * (ASTRIDE * 2) + lcol8 * 2;
    uint32_t b_lm = b_base + (warp_n * 64 + lrow) * (ASTRIDE * 2) + lcol8 * 2;

#pragma unroll 1
    for (int c = 0; c < NCH; ++c) {
        int p = c & 1;
        if (c + 1 < NCH) {
            LOADCH(c + 1, 1 - p);
            CPWAIT(1);
        } else {
            CPWAIT(0);
        }
        __syncthreads();
        uint32_t so = p * STAGE_BYTES;
#pragma unroll
        for (int ks = 0; ks < 2; ks++) {
            unsigned af[2][4];
#pragma unroll
            for (int mt = 0; mt < 2; mt++)
                LDSM4(af[mt][0], af[mt][1], af[mt][2], af[mt][3],
                      a_lm + so + mt * 16 * (ASTRIDE * 2) + ks * 32);
            unsigned bf[4][4];
#pragma unroll
            for (int np = 0; np < 4; np++)
                LDSM4(bf[np][0], bf[np][1], bf[np][2], bf[np][3],
                      b_lm + so + np * 16 * (ASTRIDE * 2) + ks * 32);
#pragma unroll
            for (int mt = 0; mt < 2; mt++)
#pragma unroll
                for (int ntile = 0; ntile < 8; ntile++)
                    mma16816(acc[mt][ntile], af[mt],
                             bf[ntile >> 1][ntile & 1],
                             bf[ntile >> 1][(ntile & 1) + 2]);
        }
        __syncthreads();
    }

    // epilogue: d = zsq + bsq - 2*cross
    int rbase = row0 + warp_m * 32;
    int cbase = n0 + warp_n * 64;
    int rlo = rbase + (lane >> 2);
    int csub = (lane & 3) * 2;
#pragma unroll
    for (int mt = 0; mt < 2; mt++) {
        int r0 = rlo + mt * 16;
        int r1 = r0 + 8;
        float zs0 = g_zsq[r0], zs1 = g_zsq[r1];
        float* dp0 = g_d + (size_t)r0 * DSTRIDE;
        float* dp1 = g_d + (size_t)r1 * DSTRIDE;
#pragma unroll
        for (int ntile = 0; ntile < 8; ntile++) {
            int col = cbase + ntile * 8 + csub;
            float b0 = g_bsq[col], b1 = g_bsq[col + 1];
            float2 v0, v1;
            v0.x = (zs0 + b0) - 2.0f * acc[mt][ntile][0];
            v0.y = (zs0 + b1) - 2.0f * acc[mt][ntile][1];
            v1.x = (zs1 + b0) - 2.0f * acc[mt][ntile][2];
            v1.y = (zs1 + b1) - 2.0f * acc[mt][ntile][3];
            *(float2*)(dp0 + col) = v0;
            *(float2*)(dp1 + col) = v1;
        }
    }

    // release this tile for the scan (generic proxy: fence + relaxed atomic)
    __threadfence();
    __syncthreads();
    if (tid == 0) atomicAdd(&g_rowflag[rb], 1);
#undef LOADCH
}

// ---------------------------------------------------------------------------
// k_post: gather z_q + indices + li, relu-sum loss over d rows (cols 0..1023)
// plus inline column 1024 (dot with book row 1024).
// ---------------------------------------------------------------------------
__global__ void __launch_bounds__(256) k_post(const float* __restrict__ z,
                                              const float* __restrict__ w,
                                              float* __restrict__ out,
                                              long long out_size) {
    __shared__ double wpart[8];
    int warp = threadIdx.x >> 5;
    int lane = threadIdx.x & 31;
    int row = blockIdx.x * 8 + warp;

    int idx = g_ind[row];
    const float* br = w + (size_t)idx * E_;
    const float* zrow = z + (size_t)row * E_;
    const float* wl = w + (size_t)NE_ * E_;      // book row 1024
    bool wz = (out_size >= (long long)ZQ_SIZE);

    float li = 0.0f, dq = 0.0f;
#pragma unroll
    for (int h = 0; h < 2; h++) {
        int off = h * 128 + 4 * lane;
        float4 q  = *(const float4*)(br + off);
        float4 zv = *(const float4*)(zrow + off);
        float4 wv = *(const float4*)(wl + off);
        float4 o;
        o.x = zv.x + (q.x - zv.x);
        o.y = zv.y + (q.y - zv.y);
        o.z = zv.z + (q.z - zv.z);
        o.w = zv.w + (q.w - zv.w);
        float dx = zv.x - q.x; li += dx * dx;
        dx = zv.y - q.y; li += dx * dx;
        dx = zv.z - q.z; li += dx * dx;
        dx = zv.w - q.w; li += dx * dx;
        dq += zv.x * wv.x + zv.y * wv.y + zv.z * wv.z + zv.w * wv.w;
        if (wz) *(float4*)(out + (size_t)row * E_ + off) = o;
    }
    li = warp_sum(li);
    dq = warp_sum(dq);
    li = __shfl_sync(0xffffffffu, li, 0);
    if (lane == 0 && out_size >= (long long)(IND_OFF + BT_))
        out[IND_OFF + row] = (float)idx;

    const float EPS_ = 1e-6f / 1024.0f;
    const float* drow = g_d + (size_t)row * DSTRIDE;
    float s = 0.0f;
#pragma unroll
    for (int m = 0; m < 8; m++) {
        float4 dv = *(const float4*)(drow + m * 128 + 4 * lane);
        s += fmaxf((li - dv.x) + EPS_, 0.0f);
        s += fmaxf((li - dv.y) + EPS_, 0.0f);
        s += fmaxf((li - dv.z) + EPS_, 0.0f);
        s += fmaxf((li - dv.w) + EPS_, 0.0f);
    }
    if (lane == 0) {
        float d1024 = (g_zsq[row] + g_bsq[NE_]) - 2.0f * dq;
        s += fmaxf((li - d1024) + EPS_, 0.0f);
    }
    s = warp_sum(s);
    if (lane == 0) wpart[warp] = (double)s;
    __syncthreads();
    if (threadIdx.x == 0) {
        double t = 0.0;
        for (int j = 0; j < 8; j++) t += wpart[j];
        g_part[blockIdx.x] = t;
    }
}

// ---------------------------------------------------------------------------
__global__ void k_final(float* __restrict__ out, long long out_size) {
    __shared__ double sd[256];
    __shared__ int smn[256], smx[256];
    int tid = threadIdx.x;
    double s = 0.0;
    for (int i = tid; i < NPOST; i += 256) s += g_part[i];
    int mn = 0x7fffffff, mx = -0x7fffffff;
    for (int i = tid; i < BT_; i += 256) {
        int v = g_ind[i];
        mn = min(mn, v);
        mx = max(mx, v);
    }
    sd[tid] = s; smn[tid] = mn; smx[tid] = mx;
    __syncthreads();
    for (int st = 128; st > 0; st >>= 1) {
        if (tid < st) {
            sd[tid] += sd[tid + st];
            smn[tid] = min(smn[tid], smn[tid + st]);
            smx[tid] = max(smx[tid], smx[tid + st]);
        }
        __syncthreads();
    }
    if (tid == 0) {
        float m = (float)(sd[0] / ((double)BT_ * (double)NB_));
        float loss = 0.25f * m + m;
        if (out_size > (long long)LOSS_OFF) out[LOSS_OFF] = loss;
        if (out_size > (long long)V_OFF)    out[V_OFF] = (float)(smx[0] - smn[0]);
    }
}

// ---------------------------------------------------------------------------
extern "C" void kernel_launch(void* const* d_in, const int* in_sizes, int n_in,
                              void* d_out, int out_size) {
    const float* z = (const float*)d_in[0];
    const float* w = (const float*)d_in[1];
    if (n_in >= 2 && in_sizes[0] == NB_ * E_ && in_sizes[1] == BT_ * E_) {
        const float* tmp = z; z = w; w = tmp;
    }
    float* out = (float*)d_out;
    long long osz = (long long)out_size;

    k_prep<<<(BT_ + NB_ + 7) / 8, 256>>>(z, w);
    k_first<<<B_, 256>>>(z, w);
    k_mega<<<16 + NGEMM, 256>>>();
    k_post<<<NPOST, 256>>>(z, w, out, osz);
    k_final<<<1, 256>>>(out, osz);
}

// round 12
// speedup vs baseline: 1.8758x; 1.0616x over previous
#include <cuda_runtime.h>
#include <cuda_fp16.h>
#include <cstdint>

#define B_   16
#define T_   1024
#define E_   256
#define NB_  1025
#define BT_  16384
#define NE_  1024

#define ZQ_SIZE  (BT_ * E_)
#define LOSS_OFF ZQ_SIZE
#define IND_OFF  (ZQ_SIZE + 1)
#define V_OFF    (IND_OFF + BT_)

#define DSTRIDE  1024
#define NTILES_N 8               // 8 * 128 = 1024 cols (col 1024 handled in k_post)
#define NTILES_R 128             // 128-row chunks, t-chunk-major: rb = tc*16 + b
#define NGEMM    (NTILES_N * NTILES_R)
#define NPOST    2048

#define K_EXT    768             // 3 products x K=256 (fp16 split)
#define KCH      32
#define NCH      (K_EXT / KCH)   // 24
#define ASTRIDE  40              // half elements per smem row (80 B)

typedef unsigned long long ull;

__device__ int    g_ind[BT_];
__device__ int    g_sink[B_];
__device__ float  g_zsq[BT_];
__device__ float  g_bsq[1152];
__device__ float  g_d[(size_t)(BT_ + 16) * DSTRIDE];   // padded rows for scan tail
__device__ double g_part[NPOST];
__device__ int    g_rowflag[NTILES_R];
__device__ __half a_ext[(size_t)BT_ * K_EXT];   // 24 MB
__device__ __half b_ext[(size_t)NB_ * K_EXT];   // 1.5 MB

static __device__ __forceinline__ float warp_sum(float v) {
#pragma unroll
    for (int o = 16; o > 0; o >>= 1) v += __shfl_xor_sync(0xffffffffu, v, o);
    return v;
}

static __device__ __forceinline__ uint32_t smem_u32(const void* p) {
    uint32_t a;
    asm("{ .reg .u64 t; cvta.to.shared.u64 t, %1; cvt.u32.u64 %0, t; }"
        : "=r"(a) : "l"(p));
    return a;
}

static __device__ __forceinline__ int ld_acq(const int* p) {
    int v;
    asm volatile("ld.acquire.gpu.global.s32 %0, [%1];" : "=r"(v) : "l"(p) : "memory");
    return v;
}

#define CP16(dst, src) \
    asm volatile("cp.async.cg.shared.global [%0], [%1], 16;" :: "r"(dst), "l"(src))
#define CPCOMMIT() asm volatile("cp.async.commit_group;" ::: "memory")
#define CPWAIT(N)  asm volatile("cp.async.wait_group %0;" :: "n"(N) : "memory")

#define LDSM4(r0, r1, r2, r3, addr) \
    asm volatile("ldmatrix.sync.aligned.m8n8.x4.shared.b16 {%0,%1,%2,%3}, [%4];" \
                 : "=r"(r0), "=r"(r1), "=r"(r2), "=r"(r3) : "r"(addr))

static __device__ __forceinline__ void mma16816(float* c, const unsigned* a,
                                                unsigned b0, unsigned b1) {
    asm volatile(
        "mma.sync.aligned.m16n8k16.row.col.f32.f16.f16.f32 "
        "{%0,%1,%2,%3}, {%4,%5,%6,%7}, {%8,%9}, {%0,%1,%2,%3};"
        : "+f"(c[0]), "+f"(c[1]), "+f"(c[2]), "+f"(c[3])
        : "r"(a[0]), "r"(a[1]), "r"(a[2]), "r"(a[3]), "r"(b0), "r"(b1));
}

// ---------------------------------------------------------------------------
// k_prep: fused row norms + fp16 2-way split + flag reset.
// A_ext segs: [z0, z0, z1]; B_ext segs: [w0, w1, w0]
// ---------------------------------------------------------------------------
__global__ void k_prep(const float* __restrict__ z, const float* __restrict__ w) {
    if (blockIdx.x == 0 && threadIdx.x < NTILES_R) g_rowflag[threadIdx.x] = 0;
    int gw = (blockIdx.x * blockDim.x + threadIdx.x) >> 5;
    int lane = threadIdx.x & 31;
    if (gw >= BT_ + NB_) return;

    const float* src = (gw < BT_) ? (z + (size_t)gw * E_ + lane * 8)
                                  : (w + (size_t)(gw - BT_) * E_ + lane * 8);
    float4 a = *(const float4*)src;
    float4 b = *(const float4*)(src + 4);
    float f[8] = {a.x, a.y, a.z, a.w, b.x, b.y, b.z, b.w};

    float s = 0.0f;
    union { __half h[8]; uint4 v; } hi, lo;
#pragma unroll
    for (int j = 0; j < 8; j++) {
        s += f[j] * f[j];
        __half h = __float2half_rn(f[j]);
        hi.h[j] = h;
        lo.h[j] = __float2half_rn(f[j] - __half2float(h));
    }
    s = warp_sum(s);

    if (gw < BT_) {
        __half* base = a_ext + (size_t)gw * K_EXT + lane * 8;
        *(uint4*)(base)       = hi.v;
        *(uint4*)(base + 256) = hi.v;
        *(uint4*)(base + 512) = lo.v;
        if (lane == 0) g_zsq[gw] = s;
    } else {
        __half* base = b_ext + (size_t)(gw - BT_) * K_EXT + lane * 8;
        *(uint4*)(base)       = hi.v;
        *(uint4*)(base + 256) = lo.v;
        *(uint4*)(base + 512) = hi.v;
        if (lane == 0) g_bsq[gw - BT_] = s;
    }
}

// ---------------------------------------------------------------------------
// argmin over d[b,0,:]
// ---------------------------------------------------------------------------
__global__ void k_first(const float* __restrict__ z, const float* __restrict__ w) {
    int b = blockIdx.x;
    __shared__ __align__(16) float zs[E_];
    __shared__ float sd[8];
    __shared__ int   sn[8];
    int tid = threadIdx.x;
    zs[tid] = z[(size_t)b * T_ * E_ + tid];
    __syncthreads();

    float zsq0 = g_zsq[b * T_];
    int warp = tid >> 5, lane = tid & 31;
    float4 za = *(const float4*)(zs + 4 * lane);
    float4 zb = *(const float4*)(zs + 128 + 4 * lane);

    float best = 3.4e38f;
    int bestn = 0x7fffffff;
    for (int n = warp; n < NB_; n += 8) {
        const float* wr = w + (size_t)n * E_;
        float4 wa = *(const float4*)(wr + 4 * lane);
        float4 wb = *(const float4*)(wr + 128 + 4 * lane);
        float p = za.x * wa.x + za.y * wa.y + za.z * wa.z + za.w * wa.w
                + zb.x * wb.x + zb.y * wb.y + zb.z * wb.z + zb.w * wb.w;
        p = warp_sum(p);
        float d = (zsq0 + g_bsq[n]) - 2.0f * p;
        if (d < best || (d == best && n < bestn)) { best = d; bestn = n; }
    }
    if (lane == 0) { sd[warp] = best; sn[warp] = bestn; }
    __syncthreads();
    if (tid == 0) {
        float bd = sd[0]; int bn = sn[0];
        for (int j = 1; j < 8; j++)
            if (sd[j] < bd || (sd[j] == bd && sn[j] < bn)) { bd = sd[j]; bn = sn[j]; }
        g_ind[b * T_] = min(bn, NE_ - 1);
    }
}

// ---------------------------------------------------------------------------
// Mega kernel (128 threads/block).
// Blocks 0..15: trailing scan (LDG + SHFL.IDX windows, generic-proxy only).
// Blocks 16..16+NGEMM: HMMA split-GEMM, warp tile 64x64 (4 warps, CTA 128x128),
// t-chunk-major tiles + flag release.
// ---------------------------------------------------------------------------
__global__ void __launch_bounds__(128) k_mega() {
    __shared__ __align__(16) __half As[2][128][ASTRIDE];
    __shared__ __align__(16) __half Bs[2][128][ASTRIDE];

    int tid = threadIdx.x;

    if (blockIdx.x < 16) {
        // ---------------- scan path ----------------
        if (tid >= 32) return;
        int b = blockIdx.x;
        int lane = tid;
        int ibb = b * T_;
        int ia = g_ind[ibb];
        float coe = 0.0f;
        const float PC = 0.1f / 1024.0f;
        int pl = min(lane, 23);
        int ready_hi = 0;
        int* gout = g_ind + ibb;
        int* sink = &g_sink[b];

#define WAITROW(tt)                                                        \
        while ((tt) >= ready_hi) {                                         \
            int fidx = ((ready_hi >> 7) << 4) + b;                         \
            while (ld_acq(&g_rowflag[fidx]) < NTILES_N) __nanosleep(64);   \
            ready_hi += 128;                                               \
        }

        float wv[4][4];
        int bs0, bs1, bs2, bs3;

        WAITROW(16 <= T_ - 1 ? 16 : T_ - 1);
        int ab0 = ia & ~3;
#pragma unroll
        for (int s = 0; s < 4; ++s)
#pragma unroll
            for (int j = 0; j < 4; ++j)
                wv[s][j] = g_d[(size_t)(ibb + 1 + s * 4 + j) * DSTRIDE + ab0 + pl];
        bs0 = ab0; bs1 = ab0; bs2 = ab0; bs3 = ab0;

        int t = 1;
#define PROCG(S, BASEVAR)                                                  \
        {                                                                  \
            int base_ = BASEVAR;                                           \
            _Pragma("unroll")                                              \
            for (int j = 0; j < 4; ++j) {                                  \
                int ib2 = min(ia + 1, NE_ - 1);                            \
                float qh = __shfl_sync(0xffffffffu, wv[S][j], ia - base_); \
                float qn = __shfl_sync(0xffffffffu, wv[S][j], ib2 - base_);\
                bool stay = (qh <= qn - coe);                              \
                ia  = stay ? ia : ib2;                                     \
                coe = stay ? coe + PC : 0.0f;                              \
                if (lane == 0) {                                           \
                    int* a_ = (t + j <= T_ - 1) ? (gout + t + j) : sink;   \
                    *a_ = ia;                                              \
                }                                                          \
            }                                                              \
            t += 4;                                                        \
            int tp = t + 12;                                               \
            if (tp + 3 <= T_) {                                            \
                int wr_ = tp + 3 <= T_ - 1 ? tp + 3 : T_ - 1;              \
                WAITROW(wr_);                                              \
                int ab_ = ia & ~3;                                         \
                _Pragma("unroll")                                          \
                for (int j = 0; j < 4; ++j)                                \
                    wv[S][j] = g_d[(size_t)(ibb + tp + j) * DSTRIDE + ab_ + pl]; \
                BASEVAR = ab_;                                             \
            }                                                              \
        }

#pragma unroll 1
        for (int it = 0; it < 64; ++it) {
            PROCG(0, bs0)
            PROCG(1, bs1)
            PROCG(2, bs2)
            PROCG(3, bs3)
        }
#undef PROCG
#undef WAITROW
        return;
    }

    // ---------------- GEMM path: 4 warps, warp tile 64x64 ----------------
    int wid = tid >> 5;
    int lane = tid & 31;
    int warp_m = wid >> 1;      // 0..1 -> 64-row slice
    int warp_n = wid & 1;       // 0..1 -> 64-col slice

    int gi = blockIdx.x - 16;
    int nt0 = gi % NTILES_N;
    int rb  = gi / NTILES_N;                 // rb = tc*16 + b
    int row0 = (rb & 15) * T_ + (rb >> 4) * 128;
    int n0   = nt0 * 128;

    float acc[4][8][4];
#pragma unroll
    for (int i = 0; i < 4; i++)
#pragma unroll
        for (int j = 0; j < 8; j++)
#pragma unroll
            for (int k = 0; k < 4; k++) acc[i][j][k] = 0.0f;

    uint32_t a_base = smem_u32(&As[0][0][0]);
    uint32_t b_base = smem_u32(&Bs[0][0][0]);
    const uint32_t STAGE_BYTES = 128 * ASTRIDE * 2;

    // loader mapping: thread t -> row tid>>2, 16B-seg tid&3; i covers +32 rows
    int lr_ = tid >> 2, seg = tid & 3;
    const __half* apz = a_ext + (size_t)(row0 + lr_) * K_EXT + seg * 8;
    const __half* bpz = b_ext + (size_t)(n0 + lr_) * K_EXT + seg * 8;
    uint32_t adst = a_base + lr_ * (ASTRIDE * 2) + seg * 16;
    uint32_t bdst = b_base + lr_ * (ASTRIDE * 2) + seg * 16;

#define LOADCH(c, buf)                                                       \
    {                                                                        \
        uint32_t so = (buf) * STAGE_BYTES;                                   \
        int ko = (c) * KCH;                                                  \
        _Pragma("unroll")                                                    \
        for (int i = 0; i < 4; i++) {                                        \
            CP16(adst + so + i * (32 * ASTRIDE * 2),                         \
                 (const char*)(apz + (size_t)i * 32 * K_EXT + ko));          \
            CP16(bdst + so + i * (32 * ASTRIDE * 2),                         \
                 (const char*)(bpz + (size_t)i * 32 * K_EXT + ko));          \
        }                                                                    \
        CPCOMMIT();                                                          \
    }

    LOADCH(0, 0);

    int lrow = lane & 15;
    int lcol8 = (lane >> 4) * 8;
    uint32_t a_lm = a_base + (warp_m * 64 + lrow) * (ASTRIDE * 2) + lcol8 * 2;
    uint32_t b_lm = b_base + (warp_n * 64 + lrow) * (ASTRIDE * 2) + lcol8 * 2;

#pragma unroll 1
    for (int c = 0; c < NCH; ++c) {
        int p = c & 1;
        if (c + 1 < NCH) {
            LOADCH(c + 1, 1 - p);
            CPWAIT(1);
        } else {
            CPWAIT(0);
        }
        __syncthreads();
        uint32_t so = p * STAGE_BYTES;
#pragma unroll
        for (int ks = 0; ks < 2; ks++) {
            unsigned af[4][4];
#pragma unroll
            for (int mt = 0; mt < 4; mt++)
                LDSM4(af[mt][0], af[mt][1], af[mt][2], af[mt][3],
                      a_lm + so + mt * 16 * (ASTRIDE * 2) + ks * 32);
            unsigned bf[4][4];
#pragma unroll
            for (int np = 0; np < 4; np++)
                LDSM4(bf[np][0], bf[np][1], bf[np][2], bf[np][3],
                      b_lm + so + np * 16 * (ASTRIDE * 2) + ks * 32);
#pragma unroll
            for (int mt = 0; mt < 4; mt++)
#pragma unroll
                for (int ntile = 0; ntile < 8; ntile++)
                    mma16816(acc[mt][ntile], af[mt],
                             bf[ntile >> 1][ntile & 1],
                             bf[ntile >> 1][(ntile & 1) + 2]);
        }
        __syncthreads();
    }

    // epilogue: d = zsq + bsq - 2*cross
    int rbase = row0 + warp_m * 64;
    int cbase = n0 + warp_n * 64;
    int rlo = rbase + (lane >> 2);
    int csub = (lane & 3) * 2;
#pragma unroll
    for (int mt = 0; mt < 4; mt++) {
        int r0 = rlo + mt * 16;
        int r1 = r0 + 8;
        float zs0 = g_zsq[r0], zs1 = g_zsq[r1];
        float* dp0 = g_d + (size_t)r0 * DSTRIDE;
        float* dp1 = g_d + (size_t)r1 * DSTRIDE;
#pragma unroll
        for (int ntile = 0; ntile < 8; ntile++) {
            int col = cbase + ntile * 8 + csub;
            float b0 = g_bsq[col], b1 = g_bsq[col + 1];
            float2 v0, v1;
            v0.x = (zs0 + b0) - 2.0f * acc[mt][ntile][0];
            v0.y = (zs0 + b1) - 2.0f * acc[mt][ntile][1];
            v1.x = (zs1 + b0) - 2.0f * acc[mt][ntile][2];
            v1.y = (zs1 + b1) - 2.0f * acc[mt][ntile][3];
            *(float2*)(dp0 + col) = v0;
            *(float2*)(dp1 + col) = v1;
        }
    }

    // release this tile for the scan (generic proxy: fence + relaxed atomic)
    __threadfence();
    __syncthreads();
    if (tid == 0) atomicAdd(&g_rowflag[rb], 1);
#undef LOADCH
}

// ---------------------------------------------------------------------------
// k_post: gather z_q + indices + li, relu-sum loss over d rows (cols 0..1023)
// plus inline column 1024 (dot with book row 1024).
// ---------------------------------------------------------------------------
__global__ void __launch_bounds__(256) k_post(const float* __restrict__ z,
                                              const float* __restrict__ w,
                                              float* __restrict__ out,
                                              long long out_size) {
    __shared__ double wpart[8];
    int warp = threadIdx.x >> 5;
    int lane = threadIdx.x & 31;
    int row = blockIdx.x * 8 + warp;

    int idx = g_ind[row];
    const float* br = w + (size_t)idx * E_;
    const float* zrow = z + (size_t)row * E_;
    const float* wl = w + (size_t)NE_ * E_;      // book row 1024
    bool wz = (out_size >= (long long)ZQ_SIZE);

    float li = 0.0f, dq = 0.0f;
#pragma unroll
    for (int h = 0; h < 2; h++) {
        int off = h * 128 + 4 * lane;
        float4 q  = *(const float4*)(br + off);
        float4 zv = *(const float4*)(zrow + off);
        float4 wv = *(const float4*)(wl + off);
        float4 o;
        o.x = zv.x + (q.x - zv.x);
        o.y = zv.y + (q.y - zv.y);
        o.z = zv.z + (q.z - zv.z);
        o.w = zv.w + (q.w - zv.w);
        float dx = zv.x - q.x; li += dx * dx;
        dx = zv.y - q.y; li += dx * dx;
        dx = zv.z - q.z; li += dx * dx;
        dx = zv.w - q.w; li += dx * dx;
        dq += zv.x * wv.x + zv.y * wv.y + zv.z * wv.z + zv.w * wv.w;
        if (wz) *(float4*)(out + (size_t)row * E_ + off) = o;
    }
    li = warp_sum(li);
    dq = warp_sum(dq);
    li = __shfl_sync(0xffffffffu, li, 0);
    if (lane == 0 && out_size >= (long long)(IND_OFF + BT_))
        out[IND_OFF + row] = (float)idx;

    const float EPS_ = 1e-6f / 1024.0f;
    const float* drow = g_d + (size_t)row * DSTRIDE;
    float s = 0.0f;
#pragma unroll
    for (int m = 0; m < 8; m++) {
        float4 dv = *(const float4*)(drow + m * 128 + 4 * lane);
        s += fmaxf((li - dv.x) + EPS_, 0.0f);
        s += fmaxf((li - dv.y) + EPS_, 0.0f);
        s += fmaxf((li - dv.z) + EPS_, 0.0f);
        s += fmaxf((li - dv.w) + EPS_, 0.0f);
    }
    if (lane == 0) {
        float d1024 = (g_zsq[row] + g_bsq[NE_]) - 2.0f * dq;
        s += fmaxf((li - d1024) + EPS_, 0.0f);
    }
    s = warp_sum(s);
    if (lane == 0) wpart[warp] = (double)s;
    __syncthreads();
    if (threadIdx.x == 0) {
        double t = 0.0;
        for (int j = 0; j < 8; j++) t += wpart[j];
        g_part[blockIdx.x] = t;
    }
}

// ---------------------------------------------------------------------------
__global__ void k_final(float* __restrict__ out, long long out_size) {
    __shared__ double sd[256];
    __shared__ int smn[256], smx[256];
    int tid = threadIdx.x;
    double s = 0.0;
    for (int i = tid; i < NPOST; i += 256) s += g_part[i];
    int mn = 0x7fffffff, mx = -0x7fffffff;
    for (int i = tid; i < BT_; i += 256) {
        int v = g_ind[i];
        mn = min(mn, v);
        mx = max(mx, v);
    }
    sd[tid] = s; smn[tid] = mn; smx[tid] = mx;
    __syncthreads();
    for (int st = 128; st > 0; st >>= 1) {
        if (tid < st) {
            sd[tid] += sd[tid + st];
            smn[tid] = min(smn[tid], smn[tid + st]);
            smx[tid] = max(smx[tid], smx[tid + st]);
        }
        __syncthreads();
    }
    if (tid == 0) {
        float m = (float)(sd[0] / ((double)BT_ * (double)NB_));
        float loss = 0.25f * m + m;
        if (out_size > (long long)LOSS_OFF) out[LOSS_OFF] = loss;
        if (out_size > (long long)V_OFF)    out[V_OFF] = (float)(smx[0] - smn[0]);
    }
}

// ---------------------------------------------------------------------------
extern "C" void kernel_launch(void* const* d_in, const int* in_sizes, int n_in,
                              void* d_out, int out_size) {
    const float* z = (const float*)d_in[0];
    const float* w = (const float*)d_in[1];
    if (n_in >= 2 && in_sizes[0] == NB_ * E_ && in_sizes[1] == BT_ * E_) {
        const float* tmp = z; z = w; w = tmp;
    }
    float* out = (float*)d_out;
    long long osz = (long long)out_size;

    k_prep<<<(BT_ + NB_ + 7) / 8, 256>>>(z, w);
    k_first<<<B_, 256>>>(z, w);
    k_mega<<<16 + NGEMM, 128>>>();
    k_post<<<NPOST, 256>>>(z, w, out, osz);
    k_final<<<1, 256>>>(out, osz);
}